// round 1
// baseline (speedup 1.0000x reference)
#include <cuda_runtime.h>
#include <math.h>

// Problem constants
#define T_DIM 100
#define B_DIM 128
#define C0 700
#define C1 256
#define C3 20
#define L_TAPS 25
#define PADR (24 * B_DIM)            // 3072 zero rows (causal left pad)
#define M_DIM (T_DIM * B_DIM)        // 12800 output rows
#define ROWS_PAD (PADR + M_DIM)      // 15872 padded rows

// -------- scratch (device globals; no allocation) --------
__device__ float g_xT[ROWS_PAD * C0];        // padded transposed input  (t,b,c)
__device__ float g_act[ROWS_PAD * C1];       // padded activations between layers
__device__ float g_conv[M_DIM * C1];         // raw conv output (pre-BN)
__device__ float g_logits[M_DIM * C3];       // layer-3 output
__device__ float g_K1[L_TAPS * C0 * C1];     // effective kernels [l][i][o]
__device__ float g_K2[L_TAPS * C1 * C1];
__device__ float g_K3[L_TAPS * C1 * C3];
__device__ float g_part[100 * 2 * 256];      // BN partial sums
__device__ float g_scale[256];
__device__ float g_shift[256];

// -------- zero the causal pad regions (every launch, deterministic) --------
__global__ void zero_pad_kernel() {
    int i = blockIdx.x * blockDim.x + threadIdx.x;
    if (i < PADR * C0) g_xT[i] = 0.f;
    if (i < PADR * C1) g_act[i] = 0.f;
}

// -------- transpose x (B,T,C) -> padded (t+24, b, c) --------
__global__ void transpose_kernel(const float* __restrict__ x) {
    int i = blockIdx.x * blockDim.x + threadIdx.x;
    if (i >= M_DIM * C0) return;
    int c = i % C0;
    int m = i / C0;          // m = t*B + b
    int t = m / B_DIM;
    int b = m % B_DIM;
    g_xT[(size_t)(m + PADR) * C0 + c] = x[((size_t)b * T_DIM + t) * C0 + c];
}

// -------- build effective DCLS kernels: Keff[l][i][o] = W[o,i]*K(l;P)/Z --------
__global__ void build_dcls(const float* __restrict__ W, const float* __restrict__ P,
                           float* __restrict__ Keff, int Cin, int Cout) {
    int idx = blockIdx.x * blockDim.x + threadIdx.x;
    if (idx >= Cin * Cout) return;
    int o = idx % Cout;
    int i = idx / Cout;
    float p = P[o * Cin + i];
    float w = W[o * Cin + i];
    float k[L_TAPS];
    float z = 0.f;
#pragma unroll
    for (int l = 0; l < L_TAPS; ++l) {
        float d = ((float)(l - 12) - p) * (1.f / 12.f);
        k[l] = expf(-0.5f * d * d);
        z += k[l];
    }
    float sc = w / (z + 1e-7f);
#pragma unroll
    for (int l = 0; l < L_TAPS; ++l)
        Keff[((size_t)l * Cin + i) * Cout + o] = k[l] * sc;
}

// -------- conv-as-GEMM: Y[m,o] = sum_l sum_i A[m + l*B, i] * Kf[l][i][o] --------
// A is the zero-padded activation buffer (ROWS_PAD x Cin).
template <int BN, int TN>
__global__ __launch_bounds__(256, 2)
void conv_gemm(const float* __restrict__ A, const float* __restrict__ Kf,
               float* __restrict__ Y, int Cin, int Cout) {
    constexpr int BM = 128, BK = 8, TM = 8;
    __shared__ float As[BK][BM + 4];
    __shared__ float Bs[BK][BN];

    int tid = threadIdx.x;
    int m0 = blockIdx.x * BM;
    int n0 = blockIdx.y * BN;
    int tr = tid / 16;           // 0..15 row group
    int tc = tid % 16;           // 0..15 col group

    float acc[TM][TN];
#pragma unroll
    for (int i = 0; i < TM; ++i)
#pragma unroll
        for (int j = 0; j < TN; ++j) acc[i][j] = 0.f;

    int ar = tid >> 1;               // 0..127
    int ac4 = (tid & 1) * 4;         // 0 or 4
    constexpr int BF4 = BK * BN / 4; // float4 count for B tile
    int br = (BF4 == 256) ? (tid / 32) : (tid / 16);
    int bc4 = (BF4 == 256) ? ((tid % 32) * 4) : ((tid % 16) * 4);

    for (int l = 0; l < L_TAPS; ++l) {
        const float* Abase = A + (size_t)(m0 + l * B_DIM) * Cin;
        const float* Kbase = Kf + (size_t)l * Cin * Cout;
        for (int i0 = 0; i0 < Cin; i0 += BK) {
            // load A tile (BM x BK), transposed into As[k][m]
            {
                float4 av = make_float4(0.f, 0.f, 0.f, 0.f);
                int ii = i0 + ac4;
                if (ii < Cin)
                    av = *(const float4*)(Abase + (size_t)ar * Cin + ii);
                As[ac4 + 0][ar] = av.x;
                As[ac4 + 1][ar] = av.y;
                As[ac4 + 2][ar] = av.z;
                As[ac4 + 3][ar] = av.w;
            }
            // load B tile (BK x BN)
            if (tid < BF4) {
                float4 bv = make_float4(0.f, 0.f, 0.f, 0.f);
                int ik = i0 + br;
                int nn = n0 + bc4;
                if (ik < Cin && nn < Cout)
                    bv = *(const float4*)(Kbase + (size_t)ik * Cout + nn);
                *(float4*)&Bs[br][bc4] = bv;
            }
            __syncthreads();
#pragma unroll
            for (int k = 0; k < BK; ++k) {
                float a[TM], b[TN];
#pragma unroll
                for (int i = 0; i < TM; ++i) a[i] = As[k][tr * TM + i];
#pragma unroll
                for (int j = 0; j < TN; ++j) b[j] = Bs[k][tc * TN + j];
#pragma unroll
                for (int i = 0; i < TM; ++i)
#pragma unroll
                    for (int j = 0; j < TN; ++j) acc[i][j] += a[i] * b[j];
            }
            __syncthreads();
        }
    }
#pragma unroll
    for (int i = 0; i < TM; ++i) {
        int m = m0 + tr * TM + i;
#pragma unroll
        for (int j = 0; j < TN; ++j) {
            int n = n0 + tc * TN + j;
            if (n < Cout) Y[(size_t)m * Cout + n] = acc[i][j];
        }
    }
}

// -------- BN stats, stage 1: per-row-slab partial sums --------
__global__ void bn_stat1(const float* __restrict__ X) {
    int c = threadIdx.x;     // 256 channels
    int bl = blockIdx.x;     // 100 slabs of 128 rows
    float s = 0.f, q = 0.f;
    for (int r = 0; r < 128; ++r) {
        float v = X[(size_t)(bl * 128 + r) * 256 + c];
        s += v;
        q += v * v;
    }
    g_part[bl * 512 + c] = s;
    g_part[bl * 512 + 256 + c] = q;
}

// -------- BN stats, stage 2: finalize scale/shift (deterministic) --------
__global__ void bn_stat2(const float* __restrict__ gamma, const float* __restrict__ beta) {
    int c = threadIdx.x;
    float s = 0.f, q = 0.f;
    for (int bl = 0; bl < 100; ++bl) {
        s += g_part[bl * 512 + c];
        q += g_part[bl * 512 + 256 + c];
    }
    float mean = s * (1.f / (float)M_DIM);
    float var = q * (1.f / (float)M_DIM) - mean * mean;
    float sc = gamma[c] * rsqrtf(var + 1e-5f);
    g_scale[c] = sc;
    g_shift[c] = beta[c] - mean * sc;
}

// -------- fused BN + ReLU, writes into padded activation buffer --------
__global__ void bn_relu(const float* __restrict__ X) {
    int i = blockIdx.x * blockDim.x + threadIdx.x;
    if (i >= M_DIM * 256) return;
    int c = i & 255;
    float v = fmaxf(g_scale[c] * X[i] + g_shift[c], 0.f);
    g_act[(size_t)PADR * 256 + i] = v;
}

// -------- softmax over 20 channels + sum over T --------
__global__ void softmax_sum(float* __restrict__ out) {
    __shared__ float red[128][20];
    int b = blockIdx.x;     // 128 batches
    int t = threadIdx.x;    // 128 threads, t < 100 active
    float acc[20];
#pragma unroll
    for (int j = 0; j < 20; ++j) acc[j] = 0.f;
    if (t < T_DIM) {
        const float* p = g_logits + ((size_t)t * B_DIM + b) * 20;
        float v[20];
        float mx = -1e30f;
#pragma unroll
        for (int j = 0; j < 20; ++j) { v[j] = p[j]; mx = fmaxf(mx, v[j]); }
        float s = 0.f;
#pragma unroll
        for (int j = 0; j < 20; ++j) { v[j] = expf(v[j] - mx); s += v[j]; }
        float inv = 1.f / s;
#pragma unroll
        for (int j = 0; j < 20; ++j) acc[j] = v[j] * inv;
    }
#pragma unroll
    for (int j = 0; j < 20; ++j) red[t][j] = acc[j];
    __syncthreads();
    for (int st = 64; st > 0; st >>= 1) {
        if (t < st)
#pragma unroll
            for (int j = 0; j < 20; ++j) red[t][j] += red[t + st][j];
        __syncthreads();
    }
    if (t < 20) out[b * 20 + t] = red[0][t];
}

extern "C" void kernel_launch(void* const* d_in, const int* in_sizes, int n_in,
                              void* d_out, int out_size) {
    const float* x      = (const float*)d_in[0];
    const float* W1     = (const float*)d_in[1];
    const float* P1     = (const float*)d_in[2];
    const float* W2     = (const float*)d_in[3];
    const float* P2     = (const float*)d_in[4];
    const float* W3     = (const float*)d_in[5];
    const float* P3     = (const float*)d_in[6];
    const float* gamma1 = (const float*)d_in[7];
    const float* beta1  = (const float*)d_in[8];
    const float* gamma2 = (const float*)d_in[9];
    const float* beta2  = (const float*)d_in[10];
    float* out = (float*)d_out;

    float *p_xT, *p_act, *p_conv, *p_logits, *p_K1, *p_K2, *p_K3;
    cudaGetSymbolAddress((void**)&p_xT, g_xT);
    cudaGetSymbolAddress((void**)&p_act, g_act);
    cudaGetSymbolAddress((void**)&p_conv, g_conv);
    cudaGetSymbolAddress((void**)&p_logits, g_logits);
    cudaGetSymbolAddress((void**)&p_K1, g_K1);
    cudaGetSymbolAddress((void**)&p_K2, g_K2);
    cudaGetSymbolAddress((void**)&p_K3, g_K3);

    zero_pad_kernel<<<(PADR * C0 + 255) / 256, 256>>>();
    transpose_kernel<<<(M_DIM * C0 + 255) / 256, 256>>>(x);
    build_dcls<<<(C0 * C1 + 255) / 256, 256>>>(W1, P1, p_K1, C0, C1);
    build_dcls<<<(C1 * C1 + 255) / 256, 256>>>(W2, P2, p_K2, C1, C1);
    build_dcls<<<(C1 * C3 + 255) / 256, 256>>>(W3, P3, p_K3, C1, C3);

    // layer 1
    conv_gemm<128, 8><<<dim3(100, 2), 256>>>(p_xT, p_K1, p_conv, C0, C1);
    bn_stat1<<<100, 256>>>(p_conv);
    bn_stat2<<<1, 256>>>(gamma1, beta1);
    bn_relu<<<(M_DIM * 256 + 255) / 256, 256>>>(p_conv);

    // layer 2
    conv_gemm<128, 8><<<dim3(100, 2), 256>>>(p_act, p_K2, p_conv, C1, C1);
    bn_stat1<<<100, 256>>>(p_conv);
    bn_stat2<<<1, 256>>>(gamma2, beta2);
    bn_relu<<<(M_DIM * 256 + 255) / 256, 256>>>(p_conv);

    // layer 3 + head
    conv_gemm<64, 4><<<dim3(100, 1), 256>>>(p_act, p_K3, p_logits, C1, C3);
    softmax_sum<<<B_DIM, 128>>>(out);
}

// round 3
// speedup vs baseline: 3.1103x; 3.1103x over previous
#include <cuda_runtime.h>
#include <cuda_bf16.h>
#include <math.h>
#include <stdint.h>

// ---------------- problem constants ----------------
#define T_DIM 100
#define B_DIM 128
#define C0 700
#define C0P 704                      // padded K per tap for layer 1 (mult of 64)
#define C1 256
#define C3 20
#define N3P 32                       // padded N for layer 3
#define L_TAPS 25
#define PADR (24 * B_DIM)            // 3072 causal zero rows
#define M_DIM (T_DIM * B_DIM)        // 12800
#define ROWS_PAD (PADR + M_DIM)      // 15872

// ---------------- device scratch ----------------
__device__ __align__(16) __nv_bfloat16 g_xhi[ROWS_PAD * C0P];
__device__ __align__(16) __nv_bfloat16 g_xlo[ROWS_PAD * C0P];
__device__ __align__(16) __nv_bfloat16 g_ahi[ROWS_PAD * C1];
__device__ __align__(16) __nv_bfloat16 g_alo[ROWS_PAD * C1];
__device__ __align__(16) float g_conv[M_DIM * C1];
__device__ __align__(16) float g_logits[M_DIM * C3];
__device__ __align__(16) __nv_bfloat16 g_K1h[L_TAPS * C1 * C0P];
__device__ __align__(16) __nv_bfloat16 g_K1l[L_TAPS * C1 * C0P];
__device__ __align__(16) __nv_bfloat16 g_K2h[L_TAPS * C1 * C1];
__device__ __align__(16) __nv_bfloat16 g_K2l[L_TAPS * C1 * C1];
__device__ __align__(16) __nv_bfloat16 g_K3h[L_TAPS * N3P * C1];
__device__ __align__(16) __nv_bfloat16 g_K3l[L_TAPS * N3P * C1];
__device__ float g_part[100 * 2 * 256];
__device__ float g_scale[256];
__device__ float g_shift[256];

// ---------------- PTX helpers (sm_80-compatible ISA only!) ----------------
__device__ __forceinline__ uint32_t smem_u32(const void* p) {
    uint32_t a;
    asm("{ .reg .u64 t; cvta.to.shared.u64 t, %1; cvt.u32.u64 %0, t; }" : "=r"(a) : "l"(p));
    return a;
}
__device__ __forceinline__ void ldsm_x4(uint32_t& r0, uint32_t& r1, uint32_t& r2, uint32_t& r3,
                                        uint32_t addr) {
    asm volatile("ldmatrix.sync.aligned.m8n8.x4.shared.b16 {%0,%1,%2,%3}, [%4];"
                 : "=r"(r0), "=r"(r1), "=r"(r2), "=r"(r3) : "r"(addr));
}
__device__ __forceinline__ void mma16816(float* c, const uint32_t* a, const uint32_t* b) {
    asm volatile(
        "mma.sync.aligned.m16n8k16.row.col.f32.bf16.bf16.f32 "
        "{%0,%1,%2,%3}, {%4,%5,%6,%7}, {%8,%9}, {%0,%1,%2,%3};"
        : "+f"(c[0]), "+f"(c[1]), "+f"(c[2]), "+f"(c[3])
        : "r"(a[0]), "r"(a[1]), "r"(a[2]), "r"(a[3]), "r"(b[0]), "r"(b[1]));
}
__device__ __forceinline__ void cp16(uint32_t s, const void* g) {
    asm volatile("cp.async.cg.shared.global [%0], [%1], 16;" :: "r"(s), "l"(g));
}
#define CP_COMMIT()  asm volatile("cp.async.commit_group;" ::: "memory")
#define CP_WAIT(n)   asm volatile("cp.async.wait_group %0;" :: "n"(n) : "memory")

// ---------------- setup kernels ----------------
__global__ void conv_input(const float* __restrict__ x) {
    int i = blockIdx.x * blockDim.x + threadIdx.x;
    if (i >= ROWS_PAD * C0P) return;
    int c = i % C0P;
    int row = i / C0P;
    float v = 0.f;
    if (row >= PADR && c < C0) {
        int m = row - PADR;
        int t = m >> 7, b = m & 127;
        v = x[((size_t)b * T_DIM + t) * C0 + c];
    }
    __nv_bfloat16 h = __float2bfloat16(v);
    g_xhi[i] = h;
    g_xlo[i] = __float2bfloat16(v - __bfloat162float(h));
}

__global__ void zero_act_pad() {
    int i = blockIdx.x * blockDim.x + threadIdx.x;
    if (i >= PADR * C1) return;
    g_ahi[i] = __float2bfloat16(0.f);
    g_alo[i] = __float2bfloat16(0.f);
}

// build DCLS kernels in [l][n][k] K-major bf16 hi/lo (zero-padded)
__global__ void build_dcls_bf16(const float* __restrict__ W, const float* __restrict__ P,
                                __nv_bfloat16* __restrict__ Kh, __nv_bfloat16* __restrict__ Kl,
                                int Cin, int Cinp, int Cout, int Npad) {
    int idx = blockIdx.x * blockDim.x + threadIdx.x;
    if (idx >= Npad * Cinp) return;
    int i = idx % Cinp;
    int n = idx / Cinp;
    if (n < Cout && i < Cin) {
        float p = P[n * Cin + i];
        float w = W[n * Cin + i];
        float k[L_TAPS], z = 0.f;
#pragma unroll
        for (int l = 0; l < L_TAPS; ++l) {
            float d = ((float)(l - 12) - p) * (1.f / 12.f);
            k[l] = expf(-0.5f * d * d);
            z += k[l];
        }
        float sc = w / (z + 1e-7f);
#pragma unroll
        for (int l = 0; l < L_TAPS; ++l) {
            float v = k[l] * sc;
            __nv_bfloat16 h = __float2bfloat16(v);
            size_t o = ((size_t)l * Npad + n) * Cinp + i;
            Kh[o] = h;
            Kl[o] = __float2bfloat16(v - __bfloat162float(h));
        }
    } else {
#pragma unroll
        for (int l = 0; l < L_TAPS; ++l) {
            size_t o = ((size_t)l * Npad + n) * Cinp + i;
            Kh[o] = __float2bfloat16(0.f);
            Kl[o] = __float2bfloat16(0.f);
        }
    }
}

// ---------------- warp-tiled mma.sync conv-GEMM ----------------
// Y[m, n] = sum_term sum_l sum_k A[m + l*128, k] * B[l][n][k]
template <int CIN, int BM, int BN, int WR, int WC, int NTOT>
__global__ __launch_bounds__(256)
void conv_mma(const __nv_bfloat16* __restrict__ Ahi, const __nv_bfloat16* __restrict__ Alo,
              const __nv_bfloat16* __restrict__ Bhi, const __nv_bfloat16* __restrict__ Blo,
              float* __restrict__ Y, int ldY, int ncol) {
    constexpr int KCH = CIN / 64;
    constexpr int NCHUNK = 3 * L_TAPS * KCH;
    constexpr int WM = BM / WR, WN = BN / WC;
    constexpr int MT = WM / 16, NT = WN / 8;
    constexpr int ASTR = 144;                // 64 bf16 + 16B pad per row
    constexpr int ASZ = BM * ASTR, BSZ = BN * ASTR;

    extern __shared__ char smem[];
    uint32_t s_as = smem_u32(smem);
    uint32_t s_bs = s_as + 2 * ASZ;

    int tid = threadIdx.x, wid = tid >> 5, lane = tid & 31;
    int m0 = blockIdx.x * BM;
    int n0 = blockIdx.y * BN;
    int warp_m = (wid % WR) * WM;
    int warp_n = (wid / WR) * WN;

    float acc[MT][NT][4];
#pragma unroll
    for (int i = 0; i < MT; ++i)
#pragma unroll
        for (int j = 0; j < NT; ++j)
#pragma unroll
            for (int q = 0; q < 4; ++q) acc[i][j][q] = 0.f;

    auto issue = [&](int c) {
        int s = c & 1;
        int term = c / (L_TAPS * KCH);
        int rem = c - term * (L_TAPS * KCH);
        int l = rem / KCH;
        int k0 = (rem - l * KCH) * 64;
        const __nv_bfloat16* Ap = (term == 2) ? Alo : Ahi;
        const __nv_bfloat16* Bp = (term == 1) ? Blo : Bhi;
        const __nv_bfloat16* Ab = Ap + (size_t)(m0 + l * B_DIM) * CIN + k0;
        const __nv_bfloat16* Bb = Bp + ((size_t)l * NTOT + n0) * CIN + k0;
        uint32_t as = s_as + s * ASZ, bs = s_bs + s * BSZ;
#pragma unroll
        for (int j = 0; j < BM * 8 / 256; ++j) {
            int tf = tid + j * 256;
            int r = tf >> 3, cc = (tf & 7) * 8;
            cp16(as + r * ASTR + cc * 2, Ab + (size_t)r * CIN + cc);
        }
#pragma unroll
        for (int j = 0; j < BN * 8 / 256; ++j) {
            int tf = tid + j * 256;
            int r = tf >> 3, cc = (tf & 7) * 8;
            cp16(bs + r * ASTR + cc * 2, Bb + (size_t)r * CIN + cc);
        }
        CP_COMMIT();
    };

    issue(0);
    for (int c = 0; c < NCHUNK; ++c) {
        if (c + 1 < NCHUNK) { issue(c + 1); CP_WAIT(1); }
        else                { CP_WAIT(0); }
        __syncthreads();
        int s = c & 1;
        uint32_t as = s_as + s * ASZ, bs = s_bs + s * BSZ;
#pragma unroll
        for (int kk = 0; kk < 4; ++kk) {
            uint32_t a[MT][4];
            uint32_t b[NT][2];
#pragma unroll
            for (int mt = 0; mt < MT; ++mt) {
                uint32_t addr = as + (warp_m + mt * 16 + (lane & 15)) * ASTR
                              + (kk * 16 + (lane >> 4) * 8) * 2;
                ldsm_x4(a[mt][0], a[mt][1], a[mt][2], a[mt][3], addr);
            }
#pragma unroll
            for (int nt = 0; nt < NT; nt += 2) {
                uint32_t addr = bs + (warp_n + (nt + (lane >> 4)) * 8 + (lane & 7)) * ASTR
                              + (kk * 16 + ((lane >> 3) & 1) * 8) * 2;
                ldsm_x4(b[nt][0], b[nt][1], b[nt + 1][0], b[nt + 1][1], addr);
            }
#pragma unroll
            for (int mt = 0; mt < MT; ++mt)
#pragma unroll
                for (int nt = 0; nt < NT; ++nt)
                    mma16816(acc[mt][nt], a[mt], b[nt]);
        }
        __syncthreads();
    }

    // epilogue: c-frag layout — c0,c1 at (row lane/4, col 2*(lane%4)); c2,c3 row+8
    int rq = lane >> 2, cq = (lane & 3) * 2;
#pragma unroll
    for (int mt = 0; mt < MT; ++mt)
#pragma unroll
        for (int nt = 0; nt < NT; ++nt) {
            int n = n0 + warp_n + nt * 8 + cq;
            if (n < ncol) {
                int m = m0 + warp_m + mt * 16 + rq;
                *(float2*)&Y[(size_t)m * ldY + n] =
                    make_float2(acc[mt][nt][0], acc[mt][nt][1]);
                *(float2*)&Y[(size_t)(m + 8) * ldY + n] =
                    make_float2(acc[mt][nt][2], acc[mt][nt][3]);
            }
        }
}

// ---------------- BN / head kernels ----------------
__global__ void bn_stat1(const float* __restrict__ X) {
    int c = threadIdx.x;
    int bl = blockIdx.x;
    float s = 0.f, q = 0.f;
    for (int r = 0; r < 128; ++r) {
        float v = X[(size_t)(bl * 128 + r) * 256 + c];
        s += v; q += v * v;
    }
    g_part[bl * 512 + c] = s;
    g_part[bl * 512 + 256 + c] = q;
}

__global__ void bn_stat2(const float* __restrict__ gamma, const float* __restrict__ beta) {
    int c = threadIdx.x;
    float s = 0.f, q = 0.f;
    for (int bl = 0; bl < 100; ++bl) {
        s += g_part[bl * 512 + c];
        q += g_part[bl * 512 + 256 + c];
    }
    float mean = s * (1.f / (float)M_DIM);
    float var = q * (1.f / (float)M_DIM) - mean * mean;
    float sc = gamma[c] * rsqrtf(var + 1e-5f);
    g_scale[c] = sc;
    g_shift[c] = beta[c] - mean * sc;
}

__global__ void bn_relu_bf16(const float* __restrict__ X) {
    int i = blockIdx.x * blockDim.x + threadIdx.x;
    if (i >= M_DIM * 256) return;
    int c = i & 255;
    float v = fmaxf(g_scale[c] * X[i] + g_shift[c], 0.f);
    __nv_bfloat16 h = __float2bfloat16(v);
    size_t o = (size_t)PADR * 256 + i;
    g_ahi[o] = h;
    g_alo[o] = __float2bfloat16(v - __bfloat162float(h));
}

__global__ void softmax_sum(float* __restrict__ out) {
    __shared__ float red[128][20];
    int b = blockIdx.x;
    int t = threadIdx.x;
    float acc[20];
#pragma unroll
    for (int j = 0; j < 20; ++j) acc[j] = 0.f;
    if (t < T_DIM) {
        const float* p = g_logits + ((size_t)t * B_DIM + b) * 20;
        float v[20], mx = -1e30f;
#pragma unroll
        for (int j = 0; j < 20; ++j) { v[j] = p[j]; mx = fmaxf(mx, v[j]); }
        float s = 0.f;
#pragma unroll
        for (int j = 0; j < 20; ++j) { v[j] = expf(v[j] - mx); s += v[j]; }
        float inv = 1.f / s;
#pragma unroll
        for (int j = 0; j < 20; ++j) acc[j] = v[j] * inv;
    }
#pragma unroll
    for (int j = 0; j < 20; ++j) red[t][j] = acc[j];
    __syncthreads();
    for (int st = 64; st > 0; st >>= 1) {
        if (t < st)
#pragma unroll
            for (int j = 0; j < 20; ++j) red[t][j] += red[t + st][j];
        __syncthreads();
    }
    if (t < 20) out[b * 20 + t] = red[0][t];
}

// ---------------- host launch ----------------
extern "C" void kernel_launch(void* const* d_in, const int* in_sizes, int n_in,
                              void* d_out, int out_size) {
    const float* x      = (const float*)d_in[0];
    const float* W1     = (const float*)d_in[1];
    const float* P1     = (const float*)d_in[2];
    const float* W2     = (const float*)d_in[3];
    const float* P2     = (const float*)d_in[4];
    const float* W3     = (const float*)d_in[5];
    const float* P3     = (const float*)d_in[6];
    const float* gamma1 = (const float*)d_in[7];
    const float* beta1  = (const float*)d_in[8];
    const float* gamma2 = (const float*)d_in[9];
    const float* beta2  = (const float*)d_in[10];
    float* out = (float*)d_out;

    __nv_bfloat16 *p_xh, *p_xl, *p_ah, *p_al, *p_K1h, *p_K1l, *p_K2h, *p_K2l, *p_K3h, *p_K3l;
    float *p_conv, *p_logits;
    cudaGetSymbolAddress((void**)&p_xh, g_xhi);
    cudaGetSymbolAddress((void**)&p_xl, g_xlo);
    cudaGetSymbolAddress((void**)&p_ah, g_ahi);
    cudaGetSymbolAddress((void**)&p_al, g_alo);
    cudaGetSymbolAddress((void**)&p_K1h, g_K1h);
    cudaGetSymbolAddress((void**)&p_K1l, g_K1l);
    cudaGetSymbolAddress((void**)&p_K2h, g_K2h);
    cudaGetSymbolAddress((void**)&p_K2l, g_K2l);
    cudaGetSymbolAddress((void**)&p_K3h, g_K3h);
    cudaGetSymbolAddress((void**)&p_K3l, g_K3l);
    cudaGetSymbolAddress((void**)&p_conv, g_conv);
    cudaGetSymbolAddress((void**)&p_logits, g_logits);

    // smem: 2*A + 2*B tiles with 144B row stride
    const int SM12 = 2 * (64 * 144) + 2 * (128 * 144);   // 55296
    const int SM3  = 2 * (128 * 144) + 2 * (32 * 144);   // 46080
    cudaFuncSetAttribute((const void*)conv_mma<C0P, 64, 128, 2, 4, 256>,
                         cudaFuncAttributeMaxDynamicSharedMemorySize, SM12);
    cudaFuncSetAttribute((const void*)conv_mma<C1, 64, 128, 2, 4, 256>,
                         cudaFuncAttributeMaxDynamicSharedMemorySize, SM12);
    cudaFuncSetAttribute((const void*)conv_mma<C1, 128, 32, 8, 1, N3P>,
                         cudaFuncAttributeMaxDynamicSharedMemorySize, SM3);

    conv_input<<<(ROWS_PAD * C0P + 255) / 256, 256>>>(x);
    zero_act_pad<<<(PADR * C1 + 255) / 256, 256>>>();
    build_dcls_bf16<<<(256 * C0P + 255) / 256, 256>>>(W1, P1, p_K1h, p_K1l, C0, C0P, 256, 256);
    build_dcls_bf16<<<(256 * C1 + 255) / 256, 256>>>(W2, P2, p_K2h, p_K2l, C1, C1, 256, 256);
    build_dcls_bf16<<<(N3P * C1 + 255) / 256, 256>>>(W3, P3, p_K3h, p_K3l, C1, C1, C3, N3P);

    // layer 1
    conv_mma<C0P, 64, 128, 2, 4, 256><<<dim3(200, 2), 256, SM12>>>(
        p_xh, p_xl, p_K1h, p_K1l, p_conv, 256, 256);
    bn_stat1<<<100, 256>>>(p_conv);
    bn_stat2<<<1, 256>>>(gamma1, beta1);
    bn_relu_bf16<<<(M_DIM * 256 + 255) / 256, 256>>>(p_conv);

    // layer 2
    conv_mma<C1, 64, 128, 2, 4, 256><<<dim3(200, 2), 256, SM12>>>(
        p_ah, p_al, p_K2h, p_K2l, p_conv, 256, 256);
    bn_stat1<<<100, 256>>>(p_conv);
    bn_stat2<<<1, 256>>>(gamma2, beta2);
    bn_relu_bf16<<<(M_DIM * 256 + 255) / 256, 256>>>(p_conv);

    // layer 3 + head
    conv_mma<C1, 128, 32, 8, 1, N3P><<<dim3(100, 1), 256, SM3>>>(
        p_ah, p_al, p_K3h, p_K3l, p_logits, 20, 20);
    softmax_sum<<<B_DIM, 128>>>(out);
}

// round 4
// speedup vs baseline: 3.3399x; 1.0738x over previous
#include <cuda_runtime.h>
#include <cuda_bf16.h>
#include <math.h>
#include <stdint.h>

// ---------------- problem constants ----------------
#define T_DIM 100
#define B_DIM 128
#define C0 700
#define C0P 704
#define C1 256
#define C3 20
#define N3P 32
#define L_TAPS 25
#define PADR (24 * B_DIM)
#define M_DIM (T_DIM * B_DIM)        // 12800
#define ROWS_PAD (PADR + M_DIM)      // 15872

// ---------------- device scratch ----------------
__device__ __align__(16) __nv_bfloat16 g_xhi[ROWS_PAD * C0P];
__device__ __align__(16) __nv_bfloat16 g_xlo[ROWS_PAD * C0P];
__device__ __align__(16) __nv_bfloat16 g_ahi[ROWS_PAD * C1];
__device__ __align__(16) __nv_bfloat16 g_alo[ROWS_PAD * C1];
__device__ __align__(16) float g_conv[6 * M_DIM * C1];     // 6 partial buffers
__device__ __align__(16) float g_logits[3 * M_DIM * C3];   // 3 partial buffers
__device__ __align__(16) __nv_bfloat16 g_K1h[L_TAPS * C1 * C0P];
__device__ __align__(16) __nv_bfloat16 g_K1l[L_TAPS * C1 * C0P];
__device__ __align__(16) __nv_bfloat16 g_K2h[L_TAPS * C1 * C1];
__device__ __align__(16) __nv_bfloat16 g_K2l[L_TAPS * C1 * C1];
__device__ __align__(16) __nv_bfloat16 g_K3h[L_TAPS * N3P * C1];
__device__ __align__(16) __nv_bfloat16 g_K3l[L_TAPS * N3P * C1];
__device__ float g_part[100 * 2 * 256];
__device__ float g_scale[256];
__device__ float g_shift[256];

// ---------------- PTX helpers (sm_80-compatible ISA only) ----------------
__device__ __forceinline__ uint32_t smem_u32(const void* p) {
    uint32_t a;
    asm("{ .reg .u64 t; cvta.to.shared.u64 t, %1; cvt.u32.u64 %0, t; }" : "=r"(a) : "l"(p));
    return a;
}
__device__ __forceinline__ void ldsm_x4(uint32_t& r0, uint32_t& r1, uint32_t& r2, uint32_t& r3,
                                        uint32_t addr) {
    asm volatile("ldmatrix.sync.aligned.m8n8.x4.shared.b16 {%0,%1,%2,%3}, [%4];"
                 : "=r"(r0), "=r"(r1), "=r"(r2), "=r"(r3) : "r"(addr));
}
__device__ __forceinline__ void mma16816(float* c, const uint32_t* a, const uint32_t* b) {
    asm volatile(
        "mma.sync.aligned.m16n8k16.row.col.f32.bf16.bf16.f32 "
        "{%0,%1,%2,%3}, {%4,%5,%6,%7}, {%8,%9}, {%0,%1,%2,%3};"
        : "+f"(c[0]), "+f"(c[1]), "+f"(c[2]), "+f"(c[3])
        : "r"(a[0]), "r"(a[1]), "r"(a[2]), "r"(a[3]), "r"(b[0]), "r"(b[1]));
}
__device__ __forceinline__ void cp16(uint32_t s, const void* g) {
    asm volatile("cp.async.cg.shared.global [%0], [%1], 16;" :: "r"(s), "l"(g));
}
#define CP_COMMIT()  asm volatile("cp.async.commit_group;" ::: "memory")
#define CP_WAIT(n)   asm volatile("cp.async.wait_group %0;" :: "n"(n) : "memory")

// ---------------- setup kernels ----------------
__global__ void conv_input(const float* __restrict__ x) {
    int i = blockIdx.x * blockDim.x + threadIdx.x;
    if (i >= ROWS_PAD * C0P) return;
    int c = i % C0P;
    int row = i / C0P;
    float v = 0.f;
    if (row >= PADR && c < C0) {
        int m = row - PADR;
        int t = m >> 7, b = m & 127;
        v = x[((size_t)b * T_DIM + t) * C0 + c];
    }
    __nv_bfloat16 h = __float2bfloat16(v);
    g_xhi[i] = h;
    g_xlo[i] = __float2bfloat16(v - __bfloat162float(h));
}

__global__ void zero_act_pad() {
    int i = blockIdx.x * blockDim.x + threadIdx.x;
    if (i >= PADR * C1) return;
    g_ahi[i] = __float2bfloat16(0.f);
    g_alo[i] = __float2bfloat16(0.f);
}

__global__ void build_dcls_bf16(const float* __restrict__ W, const float* __restrict__ P,
                                __nv_bfloat16* __restrict__ Kh, __nv_bfloat16* __restrict__ Kl,
                                int Cin, int Cinp, int Cout, int Npad) {
    int idx = blockIdx.x * blockDim.x + threadIdx.x;
    if (idx >= Npad * Cinp) return;
    int i = idx % Cinp;
    int n = idx / Cinp;
    if (n < Cout && i < Cin) {
        float p = P[n * Cin + i];
        float w = W[n * Cin + i];
        float k[L_TAPS], z = 0.f;
#pragma unroll
        for (int l = 0; l < L_TAPS; ++l) {
            float d = ((float)(l - 12) - p) * (1.f / 12.f);
            k[l] = expf(-0.5f * d * d);
            z += k[l];
        }
        float sc = w / (z + 1e-7f);
#pragma unroll
        for (int l = 0; l < L_TAPS; ++l) {
            float v = k[l] * sc;
            __nv_bfloat16 h = __float2bfloat16(v);
            size_t o = ((size_t)l * Npad + n) * Cinp + i;
            Kh[o] = h;
            Kl[o] = __float2bfloat16(v - __bfloat162float(h));
        }
    } else {
#pragma unroll
        for (int l = 0; l < L_TAPS; ++l) {
            size_t o = ((size_t)l * Npad + n) * Cinp + i;
            Kh[o] = __float2bfloat16(0.f);
            Kl[o] = __float2bfloat16(0.f);
        }
    }
}

// ---------------- warp-tiled mma.sync conv-GEMM ----------------
// grid: (M/BM, 3*KSPLIT). Each CTA computes one (m-block, term, k-part) partial
// into its own buffer: Y + blockIdx.y * M_DIM * ldY. Fully deterministic.
template <int CIN, int BM, int BN, int WR, int WC, int NTOT, int KSPLIT>
__global__ __launch_bounds__(256, 1)
void conv_mma(const __nv_bfloat16* __restrict__ Ahi, const __nv_bfloat16* __restrict__ Alo,
              const __nv_bfloat16* __restrict__ Bhi, const __nv_bfloat16* __restrict__ Blo,
              float* __restrict__ Y, int ldY, int ncol) {
    constexpr int KCH = CIN / 64;
    constexpr int NCT = L_TAPS * KCH;                 // chunks per term
    constexpr int LEN = (NCT + KSPLIT - 1) / KSPLIT;
    constexpr int WM = BM / WR, WN = BN / WC;
    constexpr int MT = WM / 16, NT = WN / 8;
    constexpr int ASTR = 144;
    constexpr int ASZ = BM * ASTR, BSZ = BN * ASTR;

    extern __shared__ char smem[];
    uint32_t s_as = smem_u32(smem);
    uint32_t s_bs = s_as + 2 * ASZ;

    int tid = threadIdx.x, wid = tid >> 5, lane = tid & 31;
    int m0 = blockIdx.x * BM;
    int term = blockIdx.y / KSPLIT;
    int part = blockIdx.y % KSPLIT;
    int q0 = part * LEN;
    int q1 = (q0 + LEN < NCT) ? q0 + LEN : NCT;
    float* Yb = Y + (size_t)blockIdx.y * M_DIM * ldY;

    const __nv_bfloat16* Ap = (term == 2) ? Alo : Ahi;
    const __nv_bfloat16* Bp = (term == 1) ? Blo : Bhi;

    int warp_m = (wid % WR) * WM;
    int warp_n = (wid / WR) * WN;

    float acc[MT][NT][4];
#pragma unroll
    for (int i = 0; i < MT; ++i)
#pragma unroll
        for (int j = 0; j < NT; ++j)
#pragma unroll
            for (int q = 0; q < 4; ++q) acc[i][j][q] = 0.f;

    auto issue = [&](int q) {
        int s = q & 1;
        int l = q / KCH;
        int k0 = (q - l * KCH) * 64;
        const __nv_bfloat16* Ab = Ap + (size_t)(m0 + l * B_DIM) * CIN + k0;
        const __nv_bfloat16* Bb = Bp + (size_t)(l * NTOT) * CIN + k0;
        uint32_t as = s_as + s * ASZ, bs = s_bs + s * BSZ;
#pragma unroll
        for (int j = 0; j < BM * 8 / 256; ++j) {
            int tf = tid + j * 256;
            int r = tf >> 3, cc = (tf & 7) * 8;
            cp16(as + r * ASTR + cc * 2, Ab + (size_t)r * CIN + cc);
        }
#pragma unroll
        for (int j = 0; j < BN * 8 / 256; ++j) {
            int tf = tid + j * 256;
            int r = tf >> 3, cc = (tf & 7) * 8;
            cp16(bs + r * ASTR + cc * 2, Bb + (size_t)r * CIN + cc);
        }
        CP_COMMIT();
    };

    issue(q0);
    for (int q = q0; q < q1; ++q) {
        if (q + 1 < q1) { issue(q + 1); CP_WAIT(1); }
        else            { CP_WAIT(0); }
        __syncthreads();
        int s = q & 1;
        uint32_t as = s_as + s * ASZ, bs = s_bs + s * BSZ;
#pragma unroll
        for (int kk = 0; kk < 4; ++kk) {
            uint32_t a[MT][4];
            uint32_t b[NT][2];
#pragma unroll
            for (int mt = 0; mt < MT; ++mt) {
                uint32_t addr = as + (warp_m + mt * 16 + (lane & 15)) * ASTR
                              + (kk * 16 + (lane >> 4) * 8) * 2;
                ldsm_x4(a[mt][0], a[mt][1], a[mt][2], a[mt][3], addr);
            }
#pragma unroll
            for (int nt = 0; nt < NT; nt += 2) {
                uint32_t addr = bs + (warp_n + (nt + (lane >> 4)) * 8 + (lane & 7)) * ASTR
                              + (kk * 16 + ((lane >> 3) & 1) * 8) * 2;
                ldsm_x4(b[nt][0], b[nt][1], b[nt + 1][0], b[nt + 1][1], addr);
            }
#pragma unroll
            for (int mt = 0; mt < MT; ++mt)
#pragma unroll
                for (int nt = 0; nt < NT; ++nt)
                    mma16816(acc[mt][nt], a[mt], b[nt]);
        }
        __syncthreads();
    }

    int rq = lane >> 2, cq = (lane & 3) * 2;
#pragma unroll
    for (int mt = 0; mt < MT; ++mt)
#pragma unroll
        for (int nt = 0; nt < NT; ++nt) {
            int n = warp_n + nt * 8 + cq;
            if (n < ncol) {
                int m = m0 + warp_m + mt * 16 + rq;
                *(float2*)&Yb[(size_t)m * ldY + n] =
                    make_float2(acc[mt][nt][0], acc[mt][nt][1]);
                *(float2*)&Yb[(size_t)(m + 8) * ldY + n] =
                    make_float2(acc[mt][nt][2], acc[mt][nt][3]);
            }
        }
}

// ---------------- BN / head kernels (sum NB partial buffers) ----------------
__global__ void bn_stat1(const float* __restrict__ X, int NB) {
    int c = threadIdx.x;
    int bl = blockIdx.x;
    float s = 0.f, q = 0.f;
    for (int r = 0; r < 128; ++r) {
        size_t idx = (size_t)(bl * 128 + r) * 256 + c;
        float v = 0.f;
        for (int b = 0; b < NB; ++b) v += X[(size_t)b * M_DIM * 256 + idx];
        s += v; q += v * v;
    }
    g_part[bl * 512 + c] = s;
    g_part[bl * 512 + 256 + c] = q;
}

__global__ void bn_stat2(const float* __restrict__ gamma, const float* __restrict__ beta) {
    int c = threadIdx.x;
    float s = 0.f, q = 0.f;
    for (int bl = 0; bl < 100; ++bl) {
        s += g_part[bl * 512 + c];
        q += g_part[bl * 512 + 256 + c];
    }
    float mean = s * (1.f / (float)M_DIM);
    float var = q * (1.f / (float)M_DIM) - mean * mean;
    float sc = gamma[c] * rsqrtf(var + 1e-5f);
    g_scale[c] = sc;
    g_shift[c] = beta[c] - mean * sc;
}

__global__ void bn_relu_bf16(const float* __restrict__ X, int NB) {
    int i = blockIdx.x * blockDim.x + threadIdx.x;
    if (i >= M_DIM * 256) return;
    int c = i & 255;
    float v = 0.f;
    for (int b = 0; b < NB; ++b) v += X[(size_t)b * M_DIM * 256 + i];
    v = fmaxf(g_scale[c] * v + g_shift[c], 0.f);
    __nv_bfloat16 h = __float2bfloat16(v);
    size_t o = (size_t)PADR * 256 + i;
    g_ahi[o] = h;
    g_alo[o] = __float2bfloat16(v - __bfloat162float(h));
}

__global__ void softmax_sum(float* __restrict__ out) {
    __shared__ float red[128][20];
    int b = blockIdx.x;
    int t = threadIdx.x;
    float acc[20];
#pragma unroll
    for (int j = 0; j < 20; ++j) acc[j] = 0.f;
    if (t < T_DIM) {
        size_t base = ((size_t)t * B_DIM + b) * 20;
        float v[20], mx = -1e30f;
#pragma unroll
        for (int j = 0; j < 20; ++j) {
            v[j] = g_logits[base + j]
                 + g_logits[(size_t)M_DIM * 20 + base + j]
                 + g_logits[(size_t)2 * M_DIM * 20 + base + j];
            mx = fmaxf(mx, v[j]);
        }
        float s = 0.f;
#pragma unroll
        for (int j = 0; j < 20; ++j) { v[j] = expf(v[j] - mx); s += v[j]; }
        float inv = 1.f / s;
#pragma unroll
        for (int j = 0; j < 20; ++j) acc[j] = v[j] * inv;
    }
#pragma unroll
    for (int j = 0; j < 20; ++j) red[t][j] = acc[j];
    __syncthreads();
    for (int st = 64; st > 0; st >>= 1) {
        if (t < st)
#pragma unroll
            for (int j = 0; j < 20; ++j) red[t][j] += red[t + st][j];
        __syncthreads();
    }
    if (t < 20) out[b * 20 + t] = red[0][t];
}

// ---------------- host launch ----------------
extern "C" void kernel_launch(void* const* d_in, const int* in_sizes, int n_in,
                              void* d_out, int out_size) {
    const float* x      = (const float*)d_in[0];
    const float* W1     = (const float*)d_in[1];
    const float* P1     = (const float*)d_in[2];
    const float* W2     = (const float*)d_in[3];
    const float* P2     = (const float*)d_in[4];
    const float* W3     = (const float*)d_in[5];
    const float* P3     = (const float*)d_in[6];
    const float* gamma1 = (const float*)d_in[7];
    const float* beta1  = (const float*)d_in[8];
    const float* gamma2 = (const float*)d_in[9];
    const float* beta2  = (const float*)d_in[10];
    float* out = (float*)d_out;

    __nv_bfloat16 *p_xh, *p_xl, *p_ah, *p_al, *p_K1h, *p_K1l, *p_K2h, *p_K2l, *p_K3h, *p_K3l;
    float *p_conv, *p_logits;
    cudaGetSymbolAddress((void**)&p_xh, g_xhi);
    cudaGetSymbolAddress((void**)&p_xl, g_xlo);
    cudaGetSymbolAddress((void**)&p_ah, g_ahi);
    cudaGetSymbolAddress((void**)&p_al, g_alo);
    cudaGetSymbolAddress((void**)&p_K1h, g_K1h);
    cudaGetSymbolAddress((void**)&p_K1l, g_K1l);
    cudaGetSymbolAddress((void**)&p_K2h, g_K2h);
    cudaGetSymbolAddress((void**)&p_K2l, g_K2l);
    cudaGetSymbolAddress((void**)&p_K3h, g_K3h);
    cudaGetSymbolAddress((void**)&p_K3l, g_K3l);
    cudaGetSymbolAddress((void**)&p_conv, g_conv);
    cudaGetSymbolAddress((void**)&p_logits, g_logits);

    const int SM12 = 2 * (128 * 144) + 2 * (256 * 144);   // 110592
    const int SM3  = 2 * (128 * 144) + 2 * (32 * 144);    // 46080
    cudaFuncSetAttribute((const void*)conv_mma<C0P, 128, 256, 4, 2, 256, 2>,
                         cudaFuncAttributeMaxDynamicSharedMemorySize, SM12);
    cudaFuncSetAttribute((const void*)conv_mma<C1, 128, 256, 4, 2, 256, 2>,
                         cudaFuncAttributeMaxDynamicSharedMemorySize, SM12);
    cudaFuncSetAttribute((const void*)conv_mma<C1, 128, 32, 8, 1, N3P, 1>,
                         cudaFuncAttributeMaxDynamicSharedMemorySize, SM3);

    conv_input<<<(ROWS_PAD * C0P + 255) / 256, 256>>>(x);
    zero_act_pad<<<(PADR * C1 + 255) / 256, 256>>>();
    build_dcls_bf16<<<(256 * C0P + 255) / 256, 256>>>(W1, P1, p_K1h, p_K1l, C0, C0P, 256, 256);
    build_dcls_bf16<<<(256 * C1 + 255) / 256, 256>>>(W2, P2, p_K2h, p_K2l, C1, C1, 256, 256);
    build_dcls_bf16<<<(N3P * C1 + 255) / 256, 256>>>(W3, P3, p_K3h, p_K3l, C1, C1, C3, N3P);

    // layer 1
    conv_mma<C0P, 128, 256, 4, 2, 256, 2><<<dim3(100, 6), 256, SM12>>>(
        p_xh, p_xl, p_K1h, p_K1l, p_conv, 256, 256);
    bn_stat1<<<100, 256>>>(p_conv, 6);
    bn_stat2<<<1, 256>>>(gamma1, beta1);
    bn_relu_bf16<<<(M_DIM * 256 + 255) / 256, 256>>>(p_conv, 6);

    // layer 2
    conv_mma<C1, 128, 256, 4, 2, 256, 2><<<dim3(100, 6), 256, SM12>>>(
        p_ah, p_al, p_K2h, p_K2l, p_conv, 256, 256);
    bn_stat1<<<100, 256>>>(p_conv, 6);
    bn_stat2<<<1, 256>>>(gamma2, beta2);
    bn_relu_bf16<<<(M_DIM * 256 + 255) / 256, 256>>>(p_conv, 6);

    // layer 3 + head
    conv_mma<C1, 128, 32, 8, 1, N3P, 1><<<dim3(100, 3), 256, SM3>>>(
        p_ah, p_al, p_K3h, p_K3l, p_logits, 20, 20);
    softmax_sum<<<B_DIM, 128>>>(out);
}

// round 5
// speedup vs baseline: 4.9986x; 1.4966x over previous
#include <cuda_runtime.h>
#include <cuda_fp16.h>
#include <math.h>
#include <stdint.h>

// ---------------- problem constants ----------------
#define T_DIM 100
#define B_DIM 128
#define C0 700
#define C0P 704
#define C1 256
#define C3 20
#define N3P 32
#define L_TAPS 25
#define PADR (24 * B_DIM)
#define M_DIM (T_DIM * B_DIM)        // 12800
#define ROWS_PAD (PADR + M_DIM)      // 15872

// ---------------- device scratch ----------------
__device__ __align__(16) __half g_xh[ROWS_PAD * C0P];      // fp16 input (single plane)
__device__ __align__(16) __half g_ah[ROWS_PAD * C1];       // fp16 activations
__device__ __align__(16) float g_conv[4 * M_DIM * C1];     // 4 partial buffers
__device__ __align__(16) float g_logits[2 * M_DIM * C3];   // 2 partial buffers
__device__ __align__(16) __half g_K1h[L_TAPS * C1 * C0P];
__device__ __align__(16) __half g_K1l[L_TAPS * C1 * C0P];
__device__ __align__(16) __half g_K2h[L_TAPS * C1 * C1];
__device__ __align__(16) __half g_K2l[L_TAPS * C1 * C1];
__device__ __align__(16) __half g_K3h[L_TAPS * N3P * C1];
__device__ __align__(16) __half g_K3l[L_TAPS * N3P * C1];
__device__ float g_part[100 * 2 * 256];
__device__ float g_scale[256];
__device__ float g_shift[256];

// ---------------- PTX helpers (sm_80-compatible ISA only) ----------------
__device__ __forceinline__ uint32_t smem_u32(const void* p) {
    uint32_t a;
    asm("{ .reg .u64 t; cvta.to.shared.u64 t, %1; cvt.u32.u64 %0, t; }" : "=r"(a) : "l"(p));
    return a;
}
__device__ __forceinline__ void ldsm_x4(uint32_t& r0, uint32_t& r1, uint32_t& r2, uint32_t& r3,
                                        uint32_t addr) {
    asm volatile("ldmatrix.sync.aligned.m8n8.x4.shared.b16 {%0,%1,%2,%3}, [%4];"
                 : "=r"(r0), "=r"(r1), "=r"(r2), "=r"(r3) : "r"(addr));
}
__device__ __forceinline__ void mma16816(float* c, const uint32_t* a, const uint32_t* b) {
    asm volatile(
        "mma.sync.aligned.m16n8k16.row.col.f32.f16.f16.f32 "
        "{%0,%1,%2,%3}, {%4,%5,%6,%7}, {%8,%9}, {%0,%1,%2,%3};"
        : "+f"(c[0]), "+f"(c[1]), "+f"(c[2]), "+f"(c[3])
        : "r"(a[0]), "r"(a[1]), "r"(a[2]), "r"(a[3]), "r"(b[0]), "r"(b[1]));
}
__device__ __forceinline__ void cp16(uint32_t s, const void* g) {
    asm volatile("cp.async.cg.shared.global [%0], [%1], 16;" :: "r"(s), "l"(g));
}
#define CP_COMMIT()  asm volatile("cp.async.commit_group;" ::: "memory")
#define CP_WAIT(n)   asm volatile("cp.async.wait_group %0;" :: "n"(n) : "memory")

// ---------------- setup kernels ----------------
__global__ void conv_input(const float* __restrict__ x) {
    int i = blockIdx.x * blockDim.x + threadIdx.x;
    if (i >= ROWS_PAD * C0P) return;
    int c = i % C0P;
    int row = i / C0P;
    float v = 0.f;
    if (row >= PADR && c < C0) {
        int m = row - PADR;
        int t = m >> 7, b = m & 127;
        v = x[((size_t)b * T_DIM + t) * C0 + c];
    }
    g_xh[i] = __float2half(v);
}

__global__ void zero_act_pad() {
    int i = blockIdx.x * blockDim.x + threadIdx.x;
    if (i >= PADR * C1) return;
    g_ah[i] = __float2half(0.f);
}

// build DCLS kernels in [l][n][k] K-major fp16 hi/lo (zero-padded)
__global__ void build_dcls_f16(const float* __restrict__ W, const float* __restrict__ P,
                               __half* __restrict__ Kh, __half* __restrict__ Kl,
                               int Cin, int Cinp, int Cout, int Npad) {
    int idx = blockIdx.x * blockDim.x + threadIdx.x;
    if (idx >= Npad * Cinp) return;
    int i = idx % Cinp;
    int n = idx / Cinp;
    if (n < Cout && i < Cin) {
        float p = P[n * Cin + i];
        float w = W[n * Cin + i];
        float k[L_TAPS], z = 0.f;
#pragma unroll
        for (int l = 0; l < L_TAPS; ++l) {
            float d = ((float)(l - 12) - p) * (1.f / 12.f);
            k[l] = expf(-0.5f * d * d);
            z += k[l];
        }
        float sc = w / (z + 1e-7f);
#pragma unroll
        for (int l = 0; l < L_TAPS; ++l) {
            float v = k[l] * sc;
            __half h = __float2half(v);
            size_t o = ((size_t)l * Npad + n) * Cinp + i;
            Kh[o] = h;
            Kl[o] = __float2half(v - __half2float(h));
        }
    } else {
#pragma unroll
        for (int l = 0; l < L_TAPS; ++l) {
            size_t o = ((size_t)l * Npad + n) * Cinp + i;
            Kh[o] = __float2half(0.f);
            Kl[o] = __float2half(0.f);
        }
    }
}

// ---------------- warp-tiled mma.sync conv-GEMM ----------------
// Chunks q in [0, 2*NCT): q<NCT uses Bh, else Bl (A plane identical).
// grid: (M/BM, NB). CTA y owns chunk range and its own partial output buffer.
template <int CIN, int BM, int BN, int WR, int WC, int NTOT, int NB>
__global__ __launch_bounds__(256, 1)
void conv_mma(const __half* __restrict__ Ah, const __half* __restrict__ Bh,
              const __half* __restrict__ Bl, float* __restrict__ Y, int ldY, int ncol) {
    constexpr int KCH = CIN / 64;
    constexpr int NCT = L_TAPS * KCH;
    constexpr int NCHUNK = 2 * NCT;
    constexpr int LEN = (NCHUNK + NB - 1) / NB;
    constexpr int WM = BM / WR, WN = BN / WC;
    constexpr int MT = WM / 16, NT = WN / 8;
    constexpr int ASTR = 144;
    constexpr int ASZ = BM * ASTR, BSZ = BN * ASTR;
    constexpr int STG = ASZ + BSZ;

    extern __shared__ char smem[];
    uint32_t s_base = smem_u32(smem);

    int tid = threadIdx.x, wid = tid >> 5, lane = tid & 31;
    int m0 = blockIdx.x * BM;
    int q0 = blockIdx.y * LEN;
    int q1 = (q0 + LEN < NCHUNK) ? q0 + LEN : NCHUNK;
    float* Yb = Y + (size_t)blockIdx.y * M_DIM * ldY;

    int warp_m = (wid % WR) * WM;
    int warp_n = (wid / WR) * WN;

    float acc[MT][NT][4];
#pragma unroll
    for (int i = 0; i < MT; ++i)
#pragma unroll
        for (int j = 0; j < NT; ++j)
#pragma unroll
            for (int q = 0; q < 4; ++q) acc[i][j][q] = 0.f;

    auto issue = [&](int q) {
        int s = q % 3;
        int term = (q >= NCT) ? 1 : 0;
        int rq = q - term * NCT;
        int l = rq / KCH;
        int k0 = (rq - l * KCH) * 64;
        const __half* Bp = term ? Bl : Bh;
        const __half* Abase = Ah + (size_t)(m0 + l * B_DIM) * CIN + k0;
        const __half* Bbase = Bp + (size_t)(l * NTOT) * CIN + k0;
        uint32_t as = s_base + s * STG;
        uint32_t bs = as + ASZ;
#pragma unroll
        for (int j = 0; j < BM * 8 / 256; ++j) {
            int tf = tid + j * 256;
            int r = tf >> 3, cc = (tf & 7) * 8;
            cp16(as + r * ASTR + cc * 2, Abase + (size_t)r * CIN + cc);
        }
#pragma unroll
        for (int j = 0; j < BN * 8 / 256; ++j) {
            int tf = tid + j * 256;
            int r = tf >> 3, cc = (tf & 7) * 8;
            cp16(bs + r * ASTR + cc * 2, Bbase + (size_t)r * CIN + cc);
        }
        CP_COMMIT();
    };

    issue(q0);
    if (q0 + 1 < q1) issue(q0 + 1);
    for (int q = q0; q < q1; ++q) {
        if (q == q1 - 1) { CP_WAIT(0); }
        else             { CP_WAIT(1); }
        __syncthreads();
        if (q + 2 < q1) issue(q + 2);
        int s = q % 3;
        uint32_t as = s_base + s * STG;
        uint32_t bs = as + ASZ;
#pragma unroll
        for (int kk = 0; kk < 4; ++kk) {
            uint32_t a[MT][4];
            uint32_t b[NT][2];
#pragma unroll
            for (int mt = 0; mt < MT; ++mt) {
                uint32_t addr = as + (warp_m + mt * 16 + (lane & 15)) * ASTR
                              + (kk * 16 + (lane >> 4) * 8) * 2;
                ldsm_x4(a[mt][0], a[mt][1], a[mt][2], a[mt][3], addr);
            }
#pragma unroll
            for (int nt = 0; nt < NT; nt += 2) {
                uint32_t addr = bs + (warp_n + (nt + (lane >> 4)) * 8 + (lane & 7)) * ASTR
                              + (kk * 16 + ((lane >> 3) & 1) * 8) * 2;
                ldsm_x4(b[nt][0], b[nt][1], b[nt + 1][0], b[nt + 1][1], addr);
            }
#pragma unroll
            for (int mt = 0; mt < MT; ++mt)
#pragma unroll
                for (int nt = 0; nt < NT; ++nt)
                    mma16816(acc[mt][nt], a[mt], b[nt]);
        }
    }

    int rq2 = lane >> 2, cq = (lane & 3) * 2;
#pragma unroll
    for (int mt = 0; mt < MT; ++mt)
#pragma unroll
        for (int nt = 0; nt < NT; ++nt) {
            int n = warp_n + nt * 8 + cq;
            if (n < ncol) {
                int m = m0 + warp_m + mt * 16 + rq2;
                *(float2*)&Yb[(size_t)m * ldY + n] =
                    make_float2(acc[mt][nt][0], acc[mt][nt][1]);
                *(float2*)&Yb[(size_t)(m + 8) * ldY + n] =
                    make_float2(acc[mt][nt][2], acc[mt][nt][3]);
            }
        }
}

// ---------------- BN / head kernels (sum NB partial buffers) ----------------
__global__ void bn_stat1(const float* __restrict__ X) {
    int c = threadIdx.x;
    int bl = blockIdx.x;
    float s = 0.f, q = 0.f;
    for (int r = 0; r < 128; ++r) {
        size_t idx = (size_t)(bl * 128 + r) * 256 + c;
        float v = X[idx] + X[(size_t)M_DIM * 256 + idx]
                + X[(size_t)2 * M_DIM * 256 + idx] + X[(size_t)3 * M_DIM * 256 + idx];
        s += v; q += v * v;
    }
    g_part[bl * 512 + c] = s;
    g_part[bl * 512 + 256 + c] = q;
}

__global__ void bn_stat2(const float* __restrict__ gamma, const float* __restrict__ beta) {
    int c = threadIdx.x;
    float s = 0.f, q = 0.f;
    for (int bl = 0; bl < 100; ++bl) {
        s += g_part[bl * 512 + c];
        q += g_part[bl * 512 + 256 + c];
    }
    float mean = s * (1.f / (float)M_DIM);
    float var = q * (1.f / (float)M_DIM) - mean * mean;
    float sc = gamma[c] * rsqrtf(var + 1e-5f);
    g_scale[c] = sc;
    g_shift[c] = beta[c] - mean * sc;
}

__global__ void bn_relu_f16(const float* __restrict__ X) {
    int i = blockIdx.x * blockDim.x + threadIdx.x;
    if (i >= M_DIM * 256) return;
    int c = i & 255;
    float v = X[i] + X[(size_t)M_DIM * 256 + i]
            + X[(size_t)2 * M_DIM * 256 + i] + X[(size_t)3 * M_DIM * 256 + i];
    v = fmaxf(g_scale[c] * v + g_shift[c], 0.f);
    g_ah[(size_t)PADR * 256 + i] = __float2half(v);
}

__global__ void softmax_sum(float* __restrict__ out) {
    __shared__ float red[128][20];
    int b = blockIdx.x;
    int t = threadIdx.x;
    float acc[20];
#pragma unroll
    for (int j = 0; j < 20; ++j) acc[j] = 0.f;
    if (t < T_DIM) {
        size_t base = ((size_t)t * B_DIM + b) * 20;
        float v[20], mx = -1e30f;
#pragma unroll
        for (int j = 0; j < 20; ++j) {
            v[j] = g_logits[base + j] + g_logits[(size_t)M_DIM * 20 + base + j];
            mx = fmaxf(mx, v[j]);
        }
        float s = 0.f;
#pragma unroll
        for (int j = 0; j < 20; ++j) { v[j] = expf(v[j] - mx); s += v[j]; }
        float inv = 1.f / s;
#pragma unroll
        for (int j = 0; j < 20; ++j) acc[j] = v[j] * inv;
    }
#pragma unroll
    for (int j = 0; j < 20; ++j) red[t][j] = acc[j];
    __syncthreads();
    for (int st = 64; st > 0; st >>= 1) {
        if (t < st)
#pragma unroll
            for (int j = 0; j < 20; ++j) red[t][j] += red[t + st][j];
        __syncthreads();
    }
    if (t < 20) out[b * 20 + t] = red[0][t];
}

// ---------------- host launch ----------------
extern "C" void kernel_launch(void* const* d_in, const int* in_sizes, int n_in,
                              void* d_out, int out_size) {
    const float* x      = (const float*)d_in[0];
    const float* W1     = (const float*)d_in[1];
    const float* P1     = (const float*)d_in[2];
    const float* W2     = (const float*)d_in[3];
    const float* P2     = (const float*)d_in[4];
    const float* W3     = (const float*)d_in[5];
    const float* P3     = (const float*)d_in[6];
    const float* gamma1 = (const float*)d_in[7];
    const float* beta1  = (const float*)d_in[8];
    const float* gamma2 = (const float*)d_in[9];
    const float* beta2  = (const float*)d_in[10];
    float* out = (float*)d_out;

    __half *p_xh, *p_ah, *p_K1h, *p_K1l, *p_K2h, *p_K2l, *p_K3h, *p_K3l;
    float *p_conv, *p_logits;
    cudaGetSymbolAddress((void**)&p_xh, g_xh);
    cudaGetSymbolAddress((void**)&p_ah, g_ah);
    cudaGetSymbolAddress((void**)&p_K1h, g_K1h);
    cudaGetSymbolAddress((void**)&p_K1l, g_K1l);
    cudaGetSymbolAddress((void**)&p_K2h, g_K2h);
    cudaGetSymbolAddress((void**)&p_K2l, g_K2l);
    cudaGetSymbolAddress((void**)&p_K3h, g_K3h);
    cudaGetSymbolAddress((void**)&p_K3l, g_K3l);
    cudaGetSymbolAddress((void**)&p_conv, g_conv);
    cudaGetSymbolAddress((void**)&p_logits, g_logits);

    const int SM12 = 3 * (128 * 144 + 256 * 144);   // 165888
    const int SM3  = 3 * (128 * 144 + 32 * 144);    // 69120
    cudaFuncSetAttribute((const void*)conv_mma<C0P, 128, 256, 4, 2, 256, 4>,
                         cudaFuncAttributeMaxDynamicSharedMemorySize, SM12);
    cudaFuncSetAttribute((const void*)conv_mma<C1, 128, 256, 4, 2, 256, 4>,
                         cudaFuncAttributeMaxDynamicSharedMemorySize, SM12);
    cudaFuncSetAttribute((const void*)conv_mma<C1, 128, 32, 8, 1, N3P, 2>,
                         cudaFuncAttributeMaxDynamicSharedMemorySize, SM3);

    conv_input<<<(ROWS_PAD * C0P + 255) / 256, 256>>>(x);
    zero_act_pad<<<(PADR * C1 + 255) / 256, 256>>>();
    build_dcls_f16<<<(256 * C0P + 255) / 256, 256>>>(W1, P1, p_K1h, p_K1l, C0, C0P, 256, 256);
    build_dcls_f16<<<(256 * C1 + 255) / 256, 256>>>(W2, P2, p_K2h, p_K2l, C1, C1, 256, 256);
    build_dcls_f16<<<(N3P * C1 + 255) / 256, 256>>>(W3, P3, p_K3h, p_K3l, C1, C1, C3, N3P);

    // layer 1
    conv_mma<C0P, 128, 256, 4, 2, 256, 4><<<dim3(100, 4), 256, SM12>>>(
        p_xh, p_K1h, p_K1l, p_conv, 256, 256);
    bn_stat1<<<100, 256>>>(p_conv);
    bn_stat2<<<1, 256>>>(gamma1, beta1);
    bn_relu_f16<<<(M_DIM * 256 + 255) / 256, 256>>>(p_conv);

    // layer 2
    conv_mma<C1, 128, 256, 4, 2, 256, 4><<<dim3(100, 4), 256, SM12>>>(
        p_ah, p_K2h, p_K2l, p_conv, 256, 256);
    bn_stat1<<<100, 256>>>(p_conv);
    bn_stat2<<<1, 256>>>(gamma2, beta2);
    bn_relu_f16<<<(M_DIM * 256 + 255) / 256, 256>>>(p_conv);

    // layer 3 + head
    conv_mma<C1, 128, 32, 8, 1, N3P, 2><<<dim3(100, 2), 256, SM3>>>(
        p_ah, p_K3h, p_K3l, p_logits, 20, 20);
    softmax_sum<<<B_DIM, 128>>>(out);
}

// round 6
// speedup vs baseline: 8.4819x; 1.6969x over previous
#include <cuda_runtime.h>
#include <cuda_fp16.h>
#include <math.h>
#include <stdint.h>

// ---------------- problem constants ----------------
#define T_DIM 100
#define B_DIM 128
#define C0 700
#define C0P 704
#define C1 256
#define C3 20
#define N3P 32
#define L_TAPS 25
#define PADR (24 * B_DIM)
#define M_DIM (T_DIM * B_DIM)        // 12800
#define ROWS_PAD (PADR + M_DIM)      // 15872

// ---------------- device scratch ----------------
__device__ __align__(16) __half g_xh[ROWS_PAD * C0P];      // fp16 input
__device__ __align__(16) __half g_ah[ROWS_PAD * C1];       // fp16 activations
__device__ __align__(16) float g_conv[4 * M_DIM * C1];     // 4 partial buffers
__device__ __align__(16) float g_logits[2 * M_DIM * C3];   // 2 partial buffers
__device__ __align__(16) __half g_K1h[L_TAPS * C1 * C0P];
__device__ __align__(16) __half g_K2h[L_TAPS * C1 * C1];
__device__ __align__(16) __half g_K3h[L_TAPS * N3P * C1];
__device__ __align__(16) __half g_K3l[L_TAPS * N3P * C1];
__device__ float g_part[100 * 2 * 256];
__device__ float g_scale[256];
__device__ float g_shift[256];

// ---------------- PTX helpers (sm_80-compatible ISA only) ----------------
__device__ __forceinline__ uint32_t smem_u32(const void* p) {
    uint32_t a;
    asm("{ .reg .u64 t; cvta.to.shared.u64 t, %1; cvt.u32.u64 %0, t; }" : "=r"(a) : "l"(p));
    return a;
}
__device__ __forceinline__ void ldsm_x4(uint32_t& r0, uint32_t& r1, uint32_t& r2, uint32_t& r3,
                                        uint32_t addr) {
    asm volatile("ldmatrix.sync.aligned.m8n8.x4.shared.b16 {%0,%1,%2,%3}, [%4];"
                 : "=r"(r0), "=r"(r1), "=r"(r2), "=r"(r3) : "r"(addr));
}
__device__ __forceinline__ void mma16816(float* c, const uint32_t* a, const uint32_t* b) {
    asm volatile(
        "mma.sync.aligned.m16n8k16.row.col.f32.f16.f16.f32 "
        "{%0,%1,%2,%3}, {%4,%5,%6,%7}, {%8,%9}, {%0,%1,%2,%3};"
        : "+f"(c[0]), "+f"(c[1]), "+f"(c[2]), "+f"(c[3])
        : "r"(a[0]), "r"(a[1]), "r"(a[2]), "r"(a[3]), "r"(b[0]), "r"(b[1]));
}
__device__ __forceinline__ void cp16(uint32_t s, const void* g) {
    asm volatile("cp.async.cg.shared.global [%0], [%1], 16;" :: "r"(s), "l"(g));
}
#define CP_COMMIT()  asm volatile("cp.async.commit_group;" ::: "memory")
#define CP_WAIT(n)   asm volatile("cp.async.wait_group %0;" :: "n"(n) : "memory")

// ---------------- setup kernels ----------------
__global__ void conv_input(const float* __restrict__ x) {
    int i = blockIdx.x * blockDim.x + threadIdx.x;
    if (i >= ROWS_PAD * C0P) return;
    int c = i % C0P;
    int row = i / C0P;
    float v = 0.f;
    if (row >= PADR && c < C0) {
        int m = row - PADR;
        int t = m >> 7, b = m & 127;
        v = x[((size_t)b * T_DIM + t) * C0 + c];
    }
    g_xh[i] = __float2half(v);
}

__global__ void zero_act_pad() {
    int i = blockIdx.x * blockDim.x + threadIdx.x;
    if (i >= PADR * C1) return;
    g_ah[i] = __float2half(0.f);
}

// build DCLS kernels [l][n][k] K-major fp16; optional residual plane
__global__ void build_dcls_f16(const float* __restrict__ W, const float* __restrict__ P,
                               __half* __restrict__ Kh, __half* __restrict__ Kl,
                               int Cin, int Cinp, int Cout, int Npad) {
    int idx = blockIdx.x * blockDim.x + threadIdx.x;
    if (idx >= Npad * Cinp) return;
    int i = idx % Cinp;
    int n = idx / Cinp;
    if (n < Cout && i < Cin) {
        float p = P[n * Cin + i];
        float w = W[n * Cin + i];
        float k[L_TAPS], z = 0.f;
#pragma unroll
        for (int l = 0; l < L_TAPS; ++l) {
            float d = ((float)(l - 12) - p) * (1.f / 12.f);
            k[l] = expf(-0.5f * d * d);
            z += k[l];
        }
        float sc = w / (z + 1e-7f);
#pragma unroll
        for (int l = 0; l < L_TAPS; ++l) {
            float v = k[l] * sc;
            __half h = __float2half(v);
            size_t o = ((size_t)l * Npad + n) * Cinp + i;
            Kh[o] = h;
            if (Kl) Kl[o] = __float2half(v - __half2float(h));
        }
    } else {
#pragma unroll
        for (int l = 0; l < L_TAPS; ++l) {
            size_t o = ((size_t)l * Npad + n) * Cinp + i;
            Kh[o] = __float2half(0.f);
            if (Kl) Kl[o] = __float2half(0.f);
        }
    }
}

// ---------------- warp-tiled mma.sync conv-GEMM ----------------
// NCHUNK = TERMS*NCT chunks of K=64; chunk q<NCT uses Bh else Bl.
// grid: (M/BM, NB); CTA y owns a chunk range + its own partial buffer.
template <int CIN, int BM, int BN, int WR, int WC, int NTOT, int NB, int TERMS>
__global__ __launch_bounds__(256, 1)
void conv_mma(const __half* __restrict__ Ah, const __half* __restrict__ Bh,
              const __half* __restrict__ Bl, float* __restrict__ Y, int ldY, int ncol) {
    constexpr int KCH = CIN / 64;
    constexpr int NCT = L_TAPS * KCH;
    constexpr int NCHUNK = TERMS * NCT;
    constexpr int LEN = (NCHUNK + NB - 1) / NB;
    constexpr int WM = BM / WR, WN = BN / WC;
    constexpr int MT = WM / 16, NT = WN / 8;
    constexpr int ASTR = 144;
    constexpr int ASZ = BM * ASTR, BSZ = BN * ASTR;
    constexpr int STG = ASZ + BSZ;

    extern __shared__ char smem[];
    uint32_t s_base = smem_u32(smem);

    int tid = threadIdx.x, wid = tid >> 5, lane = tid & 31;
    int m0 = blockIdx.x * BM;
    int q0 = blockIdx.y * LEN;
    int q1 = (q0 + LEN < NCHUNK) ? q0 + LEN : NCHUNK;
    float* Yb = Y + (size_t)blockIdx.y * M_DIM * ldY;

    int warp_m = (wid % WR) * WM;
    int warp_n = (wid / WR) * WN;

    float acc[MT][NT][4];
#pragma unroll
    for (int i = 0; i < MT; ++i)
#pragma unroll
        for (int j = 0; j < NT; ++j)
#pragma unroll
            for (int q = 0; q < 4; ++q) acc[i][j][q] = 0.f;

    auto issue = [&](int q) {
        int s = q % 3;
        int term = (q >= NCT) ? 1 : 0;
        int rq = q - term * NCT;
        int l = rq / KCH;
        int k0 = (rq - l * KCH) * 64;
        const __half* Bp = term ? Bl : Bh;
        const __half* Abase = Ah + (size_t)(m0 + l * B_DIM) * CIN + k0;
        const __half* Bbase = Bp + (size_t)(l * NTOT) * CIN + k0;
        uint32_t as = s_base + s * STG;
        uint32_t bs = as + ASZ;
#pragma unroll
        for (int j = 0; j < BM * 8 / 256; ++j) {
            int tf = tid + j * 256;
            int r = tf >> 3, cc = (tf & 7) * 8;
            cp16(as + r * ASTR + cc * 2, Abase + (size_t)r * CIN + cc);
        }
#pragma unroll
        for (int j = 0; j < BN * 8 / 256; ++j) {
            int tf = tid + j * 256;
            int r = tf >> 3, cc = (tf & 7) * 8;
            cp16(bs + r * ASTR + cc * 2, Bbase + (size_t)r * CIN + cc);
        }
        CP_COMMIT();
    };

    issue(q0);
    if (q0 + 1 < q1) issue(q0 + 1);
    for (int q = q0; q < q1; ++q) {
        if (q == q1 - 1) { CP_WAIT(0); }
        else             { CP_WAIT(1); }
        __syncthreads();
        if (q + 2 < q1) issue(q + 2);
        int s = q % 3;
        uint32_t as = s_base + s * STG;
        uint32_t bs = as + ASZ;
#pragma unroll
        for (int kk = 0; kk < 4; ++kk) {
            uint32_t a[MT][4];
            uint32_t b[NT][2];
#pragma unroll
            for (int mt = 0; mt < MT; ++mt) {
                uint32_t addr = as + (warp_m + mt * 16 + (lane & 15)) * ASTR
                              + (kk * 16 + (lane >> 4) * 8) * 2;
                ldsm_x4(a[mt][0], a[mt][1], a[mt][2], a[mt][3], addr);
            }
#pragma unroll
            for (int nt = 0; nt < NT; nt += 2) {
                uint32_t addr = bs + (warp_n + (nt + (lane >> 4)) * 8 + (lane & 7)) * ASTR
                              + (kk * 16 + ((lane >> 3) & 1) * 8) * 2;
                ldsm_x4(b[nt][0], b[nt][1], b[nt + 1][0], b[nt + 1][1], addr);
            }
#pragma unroll
            for (int mt = 0; mt < MT; ++mt)
#pragma unroll
                for (int nt = 0; nt < NT; ++nt)
                    mma16816(acc[mt][nt], a[mt], b[nt]);
        }
    }

    int rq2 = lane >> 2, cq = (lane & 3) * 2;
#pragma unroll
    for (int mt = 0; mt < MT; ++mt)
#pragma unroll
        for (int nt = 0; nt < NT; ++nt) {
            int n = warp_n + nt * 8 + cq;
            if (n < ncol) {
                int m = m0 + warp_m + mt * 16 + rq2;
                *(float2*)&Yb[(size_t)m * ldY + n] =
                    make_float2(acc[mt][nt][0], acc[mt][nt][1]);
                *(float2*)&Yb[(size_t)(m + 8) * ldY + n] =
                    make_float2(acc[mt][nt][2], acc[mt][nt][3]);
            }
        }
}

// ---------------- BN / head kernels (sum 4 partial buffers) ----------------
__global__ void bn_stat1(const float* __restrict__ X) {
    int c = threadIdx.x;
    int bl = blockIdx.x;
    float s = 0.f, q = 0.f;
    for (int r = 0; r < 128; ++r) {
        size_t idx = (size_t)(bl * 128 + r) * 256 + c;
        float v = X[idx] + X[(size_t)M_DIM * 256 + idx]
                + X[(size_t)2 * M_DIM * 256 + idx] + X[(size_t)3 * M_DIM * 256 + idx];
        s += v; q += v * v;
    }
    g_part[bl * 512 + c] = s;
    g_part[bl * 512 + 256 + c] = q;
}

__global__ void bn_stat2(const float* __restrict__ gamma, const float* __restrict__ beta) {
    int c = threadIdx.x;
    float s = 0.f, q = 0.f;
    for (int bl = 0; bl < 100; ++bl) {
        s += g_part[bl * 512 + c];
        q += g_part[bl * 512 + 256 + c];
    }
    float mean = s * (1.f / (float)M_DIM);
    float var = q * (1.f / (float)M_DIM) - mean * mean;
    float sc = gamma[c] * rsqrtf(var + 1e-5f);
    g_scale[c] = sc;
    g_shift[c] = beta[c] - mean * sc;
}

__global__ void bn_relu_f16(const float* __restrict__ X) {
    int i = blockIdx.x * blockDim.x + threadIdx.x;
    if (i >= M_DIM * 256) return;
    int c = i & 255;
    float v = X[i] + X[(size_t)M_DIM * 256 + i]
            + X[(size_t)2 * M_DIM * 256 + i] + X[(size_t)3 * M_DIM * 256 + i];
    v = fmaxf(g_scale[c] * v + g_shift[c], 0.f);
    g_ah[(size_t)PADR * 256 + i] = __float2half(v);
}

__global__ void softmax_sum(float* __restrict__ out) {
    __shared__ float red[128][20];
    int b = blockIdx.x;
    int t = threadIdx.x;
    float acc[20];
#pragma unroll
    for (int j = 0; j < 20; ++j) acc[j] = 0.f;
    if (t < T_DIM) {
        size_t base = ((size_t)t * B_DIM + b) * 20;
        float v[20], mx = -1e30f;
#pragma unroll
        for (int j = 0; j < 20; ++j) {
            v[j] = g_logits[base + j] + g_logits[(size_t)M_DIM * 20 + base + j];
            mx = fmaxf(mx, v[j]);
        }
        float s = 0.f;
#pragma unroll
        for (int j = 0; j < 20; ++j) { v[j] = expf(v[j] - mx); s += v[j]; }
        float inv = 1.f / s;
#pragma unroll
        for (int j = 0; j < 20; ++j) acc[j] = v[j] * inv;
    }
#pragma unroll
    for (int j = 0; j < 20; ++j) red[t][j] = acc[j];
    __syncthreads();
    for (int st = 64; st > 0; st >>= 1) {
        if (t < st)
#pragma unroll
            for (int j = 0; j < 20; ++j) red[t][j] += red[t + st][j];
        __syncthreads();
    }
    if (t < 20) out[b * 20 + t] = red[0][t];
}

// ---------------- host launch ----------------
extern "C" void kernel_launch(void* const* d_in, const int* in_sizes, int n_in,
                              void* d_out, int out_size) {
    const float* x      = (const float*)d_in[0];
    const float* W1     = (const float*)d_in[1];
    const float* P1     = (const float*)d_in[2];
    const float* W2     = (const float*)d_in[3];
    const float* P2     = (const float*)d_in[4];
    const float* W3     = (const float*)d_in[5];
    const float* P3     = (const float*)d_in[6];
    const float* gamma1 = (const float*)d_in[7];
    const float* beta1  = (const float*)d_in[8];
    const float* gamma2 = (const float*)d_in[9];
    const float* beta2  = (const float*)d_in[10];
    float* out = (float*)d_out;

    __half *p_xh, *p_ah, *p_K1h, *p_K2h, *p_K3h, *p_K3l;
    float *p_conv, *p_logits;
    cudaGetSymbolAddress((void**)&p_xh, g_xh);
    cudaGetSymbolAddress((void**)&p_ah, g_ah);
    cudaGetSymbolAddress((void**)&p_K1h, g_K1h);
    cudaGetSymbolAddress((void**)&p_K2h, g_K2h);
    cudaGetSymbolAddress((void**)&p_K3h, g_K3h);
    cudaGetSymbolAddress((void**)&p_K3l, g_K3l);
    cudaGetSymbolAddress((void**)&p_conv, g_conv);
    cudaGetSymbolAddress((void**)&p_logits, g_logits);

    const int SM12 = 3 * (128 * 144 + 256 * 144);   // 165888
    const int SM3  = 3 * (128 * 144 + 32 * 144);    // 69120
    cudaFuncSetAttribute((const void*)conv_mma<C0P, 128, 256, 4, 2, 256, 4, 1>,
                         cudaFuncAttributeMaxDynamicSharedMemorySize, SM12);
    cudaFuncSetAttribute((const void*)conv_mma<C1, 128, 256, 4, 2, 256, 4, 1>,
                         cudaFuncAttributeMaxDynamicSharedMemorySize, SM12);
    cudaFuncSetAttribute((const void*)conv_mma<C1, 128, 32, 8, 1, N3P, 2, 2>,
                         cudaFuncAttributeMaxDynamicSharedMemorySize, SM3);

    conv_input<<<(ROWS_PAD * C0P + 255) / 256, 256>>>(x);
    zero_act_pad<<<(PADR * C1 + 255) / 256, 256>>>();
    build_dcls_f16<<<(256 * C0P + 255) / 256, 256>>>(W1, P1, p_K1h, nullptr, C0, C0P, 256, 256);
    build_dcls_f16<<<(256 * C1 + 255) / 256, 256>>>(W2, P2, p_K2h, nullptr, C1, C1, 256, 256);
    build_dcls_f16<<<(N3P * C1 + 255) / 256, 256>>>(W3, P3, p_K3h, p_K3l, C1, C1, C3, N3P);

    // layer 1 (single fp16 term)
    conv_mma<C0P, 128, 256, 4, 2, 256, 4, 1><<<dim3(100, 4), 256, SM12>>>(
        p_xh, p_K1h, p_K1h, p_conv, 256, 256);
    bn_stat1<<<100, 256>>>(p_conv);
    bn_stat2<<<1, 256>>>(gamma1, beta1);
    bn_relu_f16<<<(M_DIM * 256 + 255) / 256, 256>>>(p_conv);

    // layer 2 (single fp16 term)
    conv_mma<C1, 128, 256, 4, 2, 256, 4, 1><<<dim3(100, 4), 256, SM12>>>(
        p_ah, p_K2h, p_K2h, p_conv, 256, 256);
    bn_stat1<<<100, 256>>>(p_conv);
    bn_stat2<<<1, 256>>>(gamma2, beta2);
    bn_relu_f16<<<(M_DIM * 256 + 255) / 256, 256>>>(p_conv);

    // layer 3 (two fp16 terms) + head
    conv_mma<C1, 128, 32, 8, 1, N3P, 2, 2><<<dim3(100, 2), 256, SM3>>>(
        p_ah, p_K3h, p_K3l, p_logits, 20, 20);
    softmax_sum<<<B_DIM, 128>>>(out);
}

// round 7
// speedup vs baseline: 9.2954x; 1.0959x over previous
#include <cuda_runtime.h>
#include <cuda_fp16.h>
#include <math.h>
#include <stdint.h>

// ---------------- problem constants ----------------
#define T_DIM 100
#define B_DIM 128
#define C0 700
#define C0P 704
#define C1 256
#define C3 20
#define N3P 32
#define L_TAPS 25
#define PADR (24 * B_DIM)
#define M_DIM (T_DIM * B_DIM)        // 12800
#define ROWS_PAD (PADR + M_DIM)      // 15872

// ---------------- device scratch ----------------
__device__ __align__(16) __half g_xh[ROWS_PAD * C0P];
__device__ __align__(16) __half g_ah[ROWS_PAD * C1];
__device__ __align__(16) float g_conv[4 * M_DIM * C1];     // 4 k-split partials
__device__ __align__(16) float g_sum[M_DIM * C1];          // summed conv
__device__ __align__(16) float g_logits[2 * M_DIM * C3];
__device__ __align__(16) __half g_K1h[L_TAPS * C1 * C0P];
__device__ __align__(16) __half g_K2h[L_TAPS * C1 * C1];
__device__ __align__(16) __half g_K3h[L_TAPS * N3P * C1];
__device__ float g_part[400 * 2 * 256];
__device__ float g_scale[256];
__device__ float g_shift[256];

// ---------------- PTX helpers (sm_80-compatible ISA only) ----------------
__device__ __forceinline__ uint32_t smem_u32(const void* p) {
    uint32_t a;
    asm("{ .reg .u64 t; cvta.to.shared.u64 t, %1; cvt.u32.u64 %0, t; }" : "=r"(a) : "l"(p));
    return a;
}
__device__ __forceinline__ void ldsm_x4(uint32_t& r0, uint32_t& r1, uint32_t& r2, uint32_t& r3,
                                        uint32_t addr) {
    asm volatile("ldmatrix.sync.aligned.m8n8.x4.shared.b16 {%0,%1,%2,%3}, [%4];"
                 : "=r"(r0), "=r"(r1), "=r"(r2), "=r"(r3) : "r"(addr));
}
__device__ __forceinline__ void mma16816(float* c, const uint32_t* a, const uint32_t* b) {
    asm volatile(
        "mma.sync.aligned.m16n8k16.row.col.f32.f16.f16.f32 "
        "{%0,%1,%2,%3}, {%4,%5,%6,%7}, {%8,%9}, {%0,%1,%2,%3};"
        : "+f"(c[0]), "+f"(c[1]), "+f"(c[2]), "+f"(c[3])
        : "r"(a[0]), "r"(a[1]), "r"(a[2]), "r"(a[3]), "r"(b[0]), "r"(b[1]));
}
__device__ __forceinline__ void cp16(uint32_t s, const void* g) {
    asm volatile("cp.async.cg.shared.global [%0], [%1], 16;" :: "r"(s), "l"(g));
}
#define CP_COMMIT()  asm volatile("cp.async.commit_group;" ::: "memory")
#define CP_WAIT(n)   asm volatile("cp.async.wait_group %0;" :: "n"(n) : "memory")

// ---------------- setup kernels ----------------
// vectorized transpose (B,T,C)->padded(t,b,c) fp16 + zero act pad
__global__ void conv_input(const float* __restrict__ x) {
    int i = blockIdx.x * blockDim.x + threadIdx.x;
    if (i >= ROWS_PAD * C0P / 2) return;
    int c2 = (i % (C0P / 2)) * 2;
    int row = i / (C0P / 2);
    float2 v = make_float2(0.f, 0.f);
    if (row >= PADR && c2 < C0) {
        int m = row - PADR;
        int t = m >> 7, b = m & 127;
        v = *(const float2*)&x[((size_t)b * T_DIM + t) * C0 + c2];
    }
    ((__half2*)g_xh)[i] = __floats2half2_rn(v.x, v.y);
    if (i < PADR * C1 / 2)
        ((__half2*)g_ah)[i] = __floats2half2_rn(0.f, 0.f);
}

// all three DCLS kernel builds in one launch; [l][n][k] K-major fp16
__device__ __forceinline__ void build_elem(const float* __restrict__ W,
                                           const float* __restrict__ P,
                                           __half* __restrict__ Kh,
                                           int Cin, int Cinp, int Cout, int Npad, int idx) {
    int i = idx % Cinp;
    int n = idx / Cinp;
    if (n < Cout && i < Cin) {
        float p = P[n * Cin + i];
        float w = W[n * Cin + i];
        float k[L_TAPS], z = 0.f;
#pragma unroll
        for (int l = 0; l < L_TAPS; ++l) {
            float d = ((float)(l - 12) - p) * (1.f / 12.f);
            k[l] = expf(-0.5f * d * d);
            z += k[l];
        }
        float sc = w / (z + 1e-7f);
#pragma unroll
        for (int l = 0; l < L_TAPS; ++l)
            Kh[((size_t)l * Npad + n) * Cinp + i] = __float2half(k[l] * sc);
    } else {
#pragma unroll
        for (int l = 0; l < L_TAPS; ++l)
            Kh[((size_t)l * Npad + n) * Cinp + i] = __float2half(0.f);
    }
}

__global__ void build_all(const float* __restrict__ W1, const float* __restrict__ P1,
                          const float* __restrict__ W2, const float* __restrict__ P2,
                          const float* __restrict__ W3, const float* __restrict__ P3) {
    int i = blockIdx.x * blockDim.x + threadIdx.x;
    const int R1 = 256 * C0P, R2 = 256 * C1, R3 = N3P * C1;
    if (i < R1) build_elem(W1, P1, g_K1h, C0, C0P, 256, 256, i);
    else if (i < R1 + R2) build_elem(W2, P2, g_K2h, C1, C1, 256, 256, i - R1);
    else if (i < R1 + R2 + R3) build_elem(W3, P3, g_K3h, C1, C1, C3, N3P, i - R1 - R2);
}

// ---------------- warp-tiled mma.sync conv-GEMM (proven R6 body) ----------------
template <int CIN, int BM, int BN, int WR, int WC, int NTOT, int NB, int TERMS>
__global__ __launch_bounds__(256, 1)
void conv_mma(const __half* __restrict__ Ah, const __half* __restrict__ Bh,
              const __half* __restrict__ Bl, float* __restrict__ Y, int ldY, int ncol) {
    constexpr int KCH = CIN / 64;
    constexpr int NCT = L_TAPS * KCH;
    constexpr int NCHUNK = TERMS * NCT;
    constexpr int LEN = (NCHUNK + NB - 1) / NB;
    constexpr int WM = BM / WR, WN = BN / WC;
    constexpr int MT = WM / 16, NT = WN / 8;
    constexpr int ASTR = 144;
    constexpr int ASZ = BM * ASTR, BSZ = BN * ASTR;
    constexpr int STG = ASZ + BSZ;

    extern __shared__ char smem[];
    uint32_t s_base = smem_u32(smem);

    int tid = threadIdx.x, wid = tid >> 5, lane = tid & 31;
    int m0 = blockIdx.x * BM;
    int q0 = blockIdx.y * LEN;
    int q1 = (q0 + LEN < NCHUNK) ? q0 + LEN : NCHUNK;
    float* Yb = Y + (size_t)blockIdx.y * M_DIM * ldY;

    int warp_m = (wid % WR) * WM;
    int warp_n = (wid / WR) * WN;

    float acc[MT][NT][4];
#pragma unroll
    for (int i = 0; i < MT; ++i)
#pragma unroll
        for (int j = 0; j < NT; ++j)
#pragma unroll
            for (int q = 0; q < 4; ++q) acc[i][j][q] = 0.f;

    auto issue = [&](int q) {
        int s = q % 3;
        int term = (q >= NCT) ? 1 : 0;
        int rq = q - term * NCT;
        int l = rq / KCH;
        int k0 = (rq - l * KCH) * 64;
        const __half* Bp = term ? Bl : Bh;
        const __half* Abase = Ah + (size_t)(m0 + l * B_DIM) * CIN + k0;
        const __half* Bbase = Bp + (size_t)(l * NTOT) * CIN + k0;
        uint32_t as = s_base + s * STG;
        uint32_t bs = as + ASZ;
#pragma unroll
        for (int j = 0; j < BM * 8 / 256; ++j) {
            int tf = tid + j * 256;
            int r = tf >> 3, cc = (tf & 7) * 8;
            cp16(as + r * ASTR + cc * 2, Abase + (size_t)r * CIN + cc);
        }
#pragma unroll
        for (int j = 0; j < BN * 8 / 256; ++j) {
            int tf = tid + j * 256;
            int r = tf >> 3, cc = (tf & 7) * 8;
            cp16(bs + r * ASTR + cc * 2, Bbase + (size_t)r * CIN + cc);
        }
        CP_COMMIT();
    };

    issue(q0);
    if (q0 + 1 < q1) issue(q0 + 1);
    for (int q = q0; q < q1; ++q) {
        if (q == q1 - 1) { CP_WAIT(0); }
        else             { CP_WAIT(1); }
        __syncthreads();
        if (q + 2 < q1) issue(q + 2);
        int s = q % 3;
        uint32_t as = s_base + s * STG;
        uint32_t bs = as + ASZ;
#pragma unroll
        for (int kk = 0; kk < 4; ++kk) {
            uint32_t a[MT][4];
            uint32_t b[NT][2];
#pragma unroll
            for (int mt = 0; mt < MT; ++mt) {
                uint32_t addr = as + (warp_m + mt * 16 + (lane & 15)) * ASTR
                              + (kk * 16 + (lane >> 4) * 8) * 2;
                ldsm_x4(a[mt][0], a[mt][1], a[mt][2], a[mt][3], addr);
            }
#pragma unroll
            for (int nt = 0; nt < NT; nt += 2) {
                uint32_t addr = bs + (warp_n + (nt + (lane >> 4)) * 8 + (lane & 7)) * ASTR
                              + (kk * 16 + ((lane >> 3) & 1) * 8) * 2;
                ldsm_x4(b[nt][0], b[nt][1], b[nt + 1][0], b[nt + 1][1], addr);
            }
#pragma unroll
            for (int mt = 0; mt < MT; ++mt)
#pragma unroll
                for (int nt = 0; nt < NT; ++nt)
                    mma16816(acc[mt][nt], a[mt], b[nt]);
        }
    }

    int rq2 = lane >> 2, cq = (lane & 3) * 2;
#pragma unroll
    for (int mt = 0; mt < MT; ++mt)
#pragma unroll
        for (int nt = 0; nt < NT; ++nt) {
            int n = warp_n + nt * 8 + cq;
            if (n < ncol) {
                int m = m0 + warp_m + mt * 16 + rq2;
                *(float2*)&Yb[(size_t)m * ldY + n] =
                    make_float2(acc[mt][nt][0], acc[mt][nt][1]);
                *(float2*)&Yb[(size_t)(m + 8) * ldY + n] =
                    make_float2(acc[mt][nt][2], acc[mt][nt][3]);
            }
        }
}

// ---------------- BN / head kernels ----------------
// 400 slabs of 32 rows: partial stats + write summed conv to g_sum
__global__ void bn_stat1(const float* __restrict__ X) {
    int c = threadIdx.x;
    int bl = blockIdx.x;     // 0..399
    float s = 0.f, q = 0.f;
    for (int r = 0; r < 32; ++r) {
        size_t idx = (size_t)(bl * 32 + r) * 256 + c;
        float v = X[idx] + X[(size_t)M_DIM * 256 + idx]
                + X[(size_t)2 * M_DIM * 256 + idx] + X[(size_t)3 * M_DIM * 256 + idx];
        s += v; q += v * v;
        g_sum[idx] = v;
    }
    g_part[bl * 512 + c] = s;
    g_part[bl * 512 + 256 + c] = q;
}

__global__ void bn_stat2(const float* __restrict__ gamma, const float* __restrict__ beta) {
    int c = threadIdx.x;
    float s = 0.f, q = 0.f;
    for (int bl = 0; bl < 400; ++bl) {
        s += g_part[bl * 512 + c];
        q += g_part[bl * 512 + 256 + c];
    }
    float mean = s * (1.f / (float)M_DIM);
    float var = q * (1.f / (float)M_DIM) - mean * mean;
    float sc = gamma[c] * rsqrtf(var + 1e-5f);
    g_scale[c] = sc;
    g_shift[c] = beta[c] - mean * sc;
}

// vectorized BN+ReLU from g_sum -> fp16 activations
__global__ void bn_relu_f16(int dummy) {
    int i = blockIdx.x * blockDim.x + threadIdx.x;
    if (i >= M_DIM * C1 / 4) return;
    float4 v = ((const float4*)g_sum)[i];
    int c = (i * 4) & 255;
    float r0 = fmaxf(g_scale[c + 0] * v.x + g_shift[c + 0], 0.f);
    float r1 = fmaxf(g_scale[c + 1] * v.y + g_shift[c + 1], 0.f);
    float r2 = fmaxf(g_scale[c + 2] * v.z + g_shift[c + 2], 0.f);
    float r3 = fmaxf(g_scale[c + 3] * v.w + g_shift[c + 3], 0.f);
    __half2 h0 = __floats2half2_rn(r0, r1);
    __half2 h1 = __floats2half2_rn(r2, r3);
    ((__half2*)g_ah)[PADR * C1 / 2 + i * 2 + 0] = h0;
    ((__half2*)g_ah)[PADR * C1 / 2 + i * 2 + 1] = h1;
}

__global__ void softmax_sum(float* __restrict__ out) {
    __shared__ float red[128][20];
    int b = blockIdx.x;
    int t = threadIdx.x;
    float acc[20];
#pragma unroll
    for (int j = 0; j < 20; ++j) acc[j] = 0.f;
    if (t < T_DIM) {
        size_t base = ((size_t)t * B_DIM + b) * 20;
        float v[20], mx = -1e30f;
#pragma unroll
        for (int j = 0; j < 20; ++j) {
            v[j] = g_logits[base + j] + g_logits[(size_t)M_DIM * 20 + base + j];
            mx = fmaxf(mx, v[j]);
        }
        float s = 0.f;
#pragma unroll
        for (int j = 0; j < 20; ++j) { v[j] = expf(v[j] - mx); s += v[j]; }
        float inv = 1.f / s;
#pragma unroll
        for (int j = 0; j < 20; ++j) acc[j] = v[j] * inv;
    }
#pragma unroll
    for (int j = 0; j < 20; ++j) red[t][j] = acc[j];
    __syncthreads();
    for (int st = 64; st > 0; st >>= 1) {
        if (t < st)
#pragma unroll
            for (int j = 0; j < 20; ++j) red[t][j] += red[t + st][j];
        __syncthreads();
    }
    if (t < 20) out[b * 20 + t] = red[0][t];
}

// ---------------- host launch ----------------
extern "C" void kernel_launch(void* const* d_in, const int* in_sizes, int n_in,
                              void* d_out, int out_size) {
    const float* x      = (const float*)d_in[0];
    const float* W1     = (const float*)d_in[1];
    const float* P1     = (const float*)d_in[2];
    const float* W2     = (const float*)d_in[3];
    const float* P2     = (const float*)d_in[4];
    const float* W3     = (const float*)d_in[5];
    const float* P3     = (const float*)d_in[6];
    const float* gamma1 = (const float*)d_in[7];
    const float* beta1  = (const float*)d_in[8];
    const float* gamma2 = (const float*)d_in[9];
    const float* beta2  = (const float*)d_in[10];
    float* out = (float*)d_out;

    __half *p_xh, *p_ah, *p_K1h, *p_K2h, *p_K3h;
    float *p_conv, *p_logits;
    cudaGetSymbolAddress((void**)&p_xh, g_xh);
    cudaGetSymbolAddress((void**)&p_ah, g_ah);
    cudaGetSymbolAddress((void**)&p_K1h, g_K1h);
    cudaGetSymbolAddress((void**)&p_K2h, g_K2h);
    cudaGetSymbolAddress((void**)&p_K3h, g_K3h);
    cudaGetSymbolAddress((void**)&p_conv, g_conv);
    cudaGetSymbolAddress((void**)&p_logits, g_logits);

    const int SM12 = 3 * (128 * 144 + 256 * 144);   // 165888
    const int SM3  = 3 * (128 * 144 + 32 * 144);    // 69120
    cudaFuncSetAttribute((const void*)conv_mma<C0P, 128, 256, 4, 2, 256, 4, 1>,
                         cudaFuncAttributeMaxDynamicSharedMemorySize, SM12);
    cudaFuncSetAttribute((const void*)conv_mma<C1, 128, 256, 4, 2, 256, 4, 1>,
                         cudaFuncAttributeMaxDynamicSharedMemorySize, SM12);
    cudaFuncSetAttribute((const void*)conv_mma<C1, 128, 32, 8, 1, N3P, 2, 1>,
                         cudaFuncAttributeMaxDynamicSharedMemorySize, SM3);

    conv_input<<<(ROWS_PAD * C0P / 2 + 255) / 256, 256>>>(x);
    {
        int total = 256 * C0P + 256 * C1 + N3P * C1;
        build_all<<<(total + 255) / 256, 256>>>(W1, P1, W2, P2, W3, P3);
    }

    // layer 1
    conv_mma<C0P, 128, 256, 4, 2, 256, 4, 1><<<dim3(100, 4), 256, SM12>>>(
        p_xh, p_K1h, p_K1h, p_conv, 256, 256);
    bn_stat1<<<400, 256>>>(p_conv);
    bn_stat2<<<1, 256>>>(gamma1, beta1);
    bn_relu_f16<<<(M_DIM * C1 / 4 + 255) / 256, 256>>>(0);

    // layer 2
    conv_mma<C1, 128, 256, 4, 2, 256, 4, 1><<<dim3(100, 4), 256, SM12>>>(
        p_ah, p_K2h, p_K2h, p_conv, 256, 256);
    bn_stat1<<<400, 256>>>(p_conv);
    bn_stat2<<<1, 256>>>(gamma2, beta2);
    bn_relu_f16<<<(M_DIM * C1 / 4 + 255) / 256, 256>>>(0);

    // layer 3 + head
    conv_mma<C1, 128, 32, 8, 1, N3P, 2, 1><<<dim3(100, 2), 256, SM3>>>(
        p_ah, p_K3h, p_K3h, p_logits, 20, 20);
    softmax_sum<<<B_DIM, 128>>>(out);
}

// round 8
// speedup vs baseline: 10.9711x; 1.1803x over previous
#include <cuda_runtime.h>
#include <cuda_fp16.h>
#include <math.h>
#include <stdint.h>

// ---------------- problem constants ----------------
#define T_DIM 100
#define B_DIM 128
#define C0 700
#define C0P 704
#define C1 256
#define C3 20
#define N3P 32
#define L_TAPS 25
#define PADR (24 * B_DIM)
#define M_DIM (T_DIM * B_DIM)        // 12800
#define ROWS_PAD (PADR + M_DIM)      // 15872

// ---------------- device scratch ----------------
__device__ __align__(16) __half g_xh[ROWS_PAD * C0P];
__device__ __align__(16) __half g_ah[ROWS_PAD * C1];
__device__ __align__(16) float g_conv[3 * M_DIM * C1];     // 3 k-split partials
__device__ __align__(16) float g_sum[M_DIM * C1];
__device__ __align__(16) float g_logits[2 * M_DIM * C3];
__device__ __align__(16) __half g_K1h[L_TAPS * C1 * C0P];
__device__ __align__(16) __half g_K2h[L_TAPS * C1 * C1];
__device__ __align__(16) __half g_K3h[L_TAPS * N3P * C1];
__device__ float g_part[400 * 2 * 256];
__device__ float g_scale[256];
__device__ float g_shift[256];

// ---------------- PTX helpers (sm_80-compatible ISA only) ----------------
__device__ __forceinline__ uint32_t smem_u32(const void* p) {
    uint32_t a;
    asm("{ .reg .u64 t; cvta.to.shared.u64 t, %1; cvt.u32.u64 %0, t; }" : "=r"(a) : "l"(p));
    return a;
}
__device__ __forceinline__ void ldsm_x4(uint32_t& r0, uint32_t& r1, uint32_t& r2, uint32_t& r3,
                                        uint32_t addr) {
    asm volatile("ldmatrix.sync.aligned.m8n8.x4.shared.b16 {%0,%1,%2,%3}, [%4];"
                 : "=r"(r0), "=r"(r1), "=r"(r2), "=r"(r3) : "r"(addr));
}
__device__ __forceinline__ void mma16816(float* c, const uint32_t* a, const uint32_t* b) {
    asm volatile(
        "mma.sync.aligned.m16n8k16.row.col.f32.f16.f16.f32 "
        "{%0,%1,%2,%3}, {%4,%5,%6,%7}, {%8,%9}, {%0,%1,%2,%3};"
        : "+f"(c[0]), "+f"(c[1]), "+f"(c[2]), "+f"(c[3])
        : "r"(a[0]), "r"(a[1]), "r"(a[2]), "r"(a[3]), "r"(b[0]), "r"(b[1]));
}
__device__ __forceinline__ void cp16(uint32_t s, const void* g) {
    asm volatile("cp.async.cg.shared.global [%0], [%1], 16;" :: "r"(s), "l"(g));
}
#define CP_COMMIT()  asm volatile("cp.async.commit_group;" ::: "memory")
#define CP_WAIT(n)   asm volatile("cp.async.wait_group %0;" :: "n"(n) : "memory")

// ---------------- setup kernels ----------------
__global__ void conv_input(const float* __restrict__ x) {
    int i = blockIdx.x * blockDim.x + threadIdx.x;
    if (i >= ROWS_PAD * C0P / 2) return;
    int c2 = (i % (C0P / 2)) * 2;
    int row = i / (C0P / 2);
    float2 v = make_float2(0.f, 0.f);
    if (row >= PADR && c2 < C0) {
        int m = row - PADR;
        int t = m >> 7, b = m & 127;
        v = *(const float2*)&x[((size_t)b * T_DIM + t) * C0 + c2];
    }
    ((__half2*)g_xh)[i] = __floats2half2_rn(v.x, v.y);
    if (i < PADR * C1 / 2)
        ((__half2*)g_ah)[i] = __floats2half2_rn(0.f, 0.f);
}

__device__ __forceinline__ void build_elem(const float* __restrict__ W,
                                           const float* __restrict__ P,
                                           __half* __restrict__ Kh,
                                           int Cin, int Cinp, int Cout, int Npad, int idx) {
    int i = idx % Cinp;
    int n = idx / Cinp;
    if (n < Cout && i < Cin) {
        float p = P[n * Cin + i];
        float w = W[n * Cin + i];
        float k[L_TAPS], z = 0.f;
#pragma unroll
        for (int l = 0; l < L_TAPS; ++l) {
            float d = ((float)(l - 12) - p) * (1.f / 12.f);
            k[l] = expf(-0.5f * d * d);
            z += k[l];
        }
        float sc = w / (z + 1e-7f);
#pragma unroll
        for (int l = 0; l < L_TAPS; ++l)
            Kh[((size_t)l * Npad + n) * Cinp + i] = __float2half(k[l] * sc);
    } else {
#pragma unroll
        for (int l = 0; l < L_TAPS; ++l)
            Kh[((size_t)l * Npad + n) * Cinp + i] = __float2half(0.f);
    }
}

__global__ void build_all(const float* __restrict__ W1, const float* __restrict__ P1,
                          const float* __restrict__ W2, const float* __restrict__ P2,
                          const float* __restrict__ W3, const float* __restrict__ P3) {
    int i = blockIdx.x * blockDim.x + threadIdx.x;
    const int R1 = 256 * C0P, R2 = 256 * C1, R3 = N3P * C1;
    if (i < R1) build_elem(W1, P1, g_K1h, C0, C0P, 256, 256, i);
    else if (i < R1 + R2) build_elem(W2, P2, g_K2h, C1, C1, 256, 256, i - R1);
    else if (i < R1 + R2 + R3) build_elem(W3, P3, g_K3h, C1, C1, C3, N3P, i - R1 - R2);
}

// ---------------- warp-tiled mma.sync conv-GEMM ----------------
// grid (M/BM, NSPLIT*KSPLIT): blockIdx.y -> (n-part, k-part).
// n-parts write disjoint columns; k-parts write separate partial buffers.
template <int CIN, int BM, int BN, int WR, int WC, int NTOT, int NSPLIT, int KSPLIT, int MAXOCC>
__global__ __launch_bounds__(256, MAXOCC)
void conv_mma(const __half* __restrict__ Ah, const __half* __restrict__ Bh,
              float* __restrict__ Y, int ldY, int ncol) {
    constexpr int KCH = CIN / 64;
    constexpr int NCHUNK = L_TAPS * KCH;
    constexpr int LEN = (NCHUNK + KSPLIT - 1) / KSPLIT;
    constexpr int WM = BM / WR, WN = BN / WC;
    constexpr int MT = WM / 16, NT = WN / 8;
    constexpr int ASTR = 144;
    constexpr int ASZ = BM * ASTR, BSZ = BN * ASTR;
    constexpr int STG = ASZ + BSZ;

    extern __shared__ char smem[];
    uint32_t s_base = smem_u32(smem);

    int tid = threadIdx.x, wid = tid >> 5, lane = tid & 31;
    int m0 = blockIdx.x * BM;
    int npart = blockIdx.y % NSPLIT;
    int kpart = blockIdx.y / NSPLIT;
    int n0 = npart * BN;
    int q0 = kpart * LEN;
    int q1 = (q0 + LEN < NCHUNK) ? q0 + LEN : NCHUNK;
    float* Yb = Y + (size_t)kpart * M_DIM * ldY;

    int warp_m = (wid % WR) * WM;
    int warp_n = (wid / WR) * WN;

    float acc[MT][NT][4];
#pragma unroll
    for (int i = 0; i < MT; ++i)
#pragma unroll
        for (int j = 0; j < NT; ++j)
#pragma unroll
            for (int q = 0; q < 4; ++q) acc[i][j][q] = 0.f;

    auto issue = [&](int q) {
        int s = q % 3;
        int l = q / KCH;
        int k0 = (q - l * KCH) * 64;
        const __half* Abase = Ah + (size_t)(m0 + l * B_DIM) * CIN + k0;
        const __half* Bbase = Bh + (size_t)(l * NTOT + n0) * CIN + k0;
        uint32_t as = s_base + s * STG;
        uint32_t bs = as + ASZ;
#pragma unroll
        for (int j = 0; j < BM * 8 / 256; ++j) {
            int tf = tid + j * 256;
            int r = tf >> 3, cc = (tf & 7) * 8;
            cp16(as + r * ASTR + cc * 2, Abase + (size_t)r * CIN + cc);
        }
#pragma unroll
        for (int j = 0; j < BN * 8 / 256; ++j) {
            int tf = tid + j * 256;
            int r = tf >> 3, cc = (tf & 7) * 8;
            cp16(bs + r * ASTR + cc * 2, Bbase + (size_t)r * CIN + cc);
        }
        CP_COMMIT();
    };

    issue(q0);
    if (q0 + 1 < q1) issue(q0 + 1);
    for (int q = q0; q < q1; ++q) {
        if (q == q1 - 1) { CP_WAIT(0); }
        else             { CP_WAIT(1); }
        __syncthreads();
        if (q + 2 < q1) issue(q + 2);
        int s = q % 3;
        uint32_t as = s_base + s * STG;
        uint32_t bs = as + ASZ;
#pragma unroll
        for (int kk = 0; kk < 4; ++kk) {
            uint32_t a[MT][4];
            uint32_t b[NT][2];
#pragma unroll
            for (int mt = 0; mt < MT; ++mt) {
                uint32_t addr = as + (warp_m + mt * 16 + (lane & 15)) * ASTR
                              + (kk * 16 + (lane >> 4) * 8) * 2;
                ldsm_x4(a[mt][0], a[mt][1], a[mt][2], a[mt][3], addr);
            }
#pragma unroll
            for (int nt = 0; nt < NT; nt += 2) {
                uint32_t addr = bs + (warp_n + (nt + (lane >> 4)) * 8 + (lane & 7)) * ASTR
                              + (kk * 16 + ((lane >> 3) & 1) * 8) * 2;
                ldsm_x4(b[nt][0], b[nt][1], b[nt + 1][0], b[nt + 1][1], addr);
            }
#pragma unroll
            for (int mt = 0; mt < MT; ++mt)
#pragma unroll
                for (int nt = 0; nt < NT; ++nt)
                    mma16816(acc[mt][nt], a[mt], b[nt]);
        }
    }

    int rq2 = lane >> 2, cq = (lane & 3) * 2;
#pragma unroll
    for (int mt = 0; mt < MT; ++mt)
#pragma unroll
        for (int nt = 0; nt < NT; ++nt) {
            int n = n0 + warp_n + nt * 8 + cq;
            if (n < ncol) {
                int m = m0 + warp_m + mt * 16 + rq2;
                *(float2*)&Yb[(size_t)m * ldY + n] =
                    make_float2(acc[mt][nt][0], acc[mt][nt][1]);
                *(float2*)&Yb[(size_t)(m + 8) * ldY + n] =
                    make_float2(acc[mt][nt][2], acc[mt][nt][3]);
            }
        }
}

// ---------------- BN / head kernels ----------------
__global__ void bn_stat1(const float* __restrict__ X) {
    int c = threadIdx.x;
    int bl = blockIdx.x;     // 0..399, 32 rows each
    float s = 0.f, q = 0.f;
#pragma unroll 4
    for (int r = 0; r < 32; ++r) {
        size_t idx = (size_t)(bl * 32 + r) * 256 + c;
        float v = X[idx] + X[(size_t)M_DIM * 256 + idx] + X[(size_t)2 * M_DIM * 256 + idx];
        s += v; q += v * v;
        g_sum[idx] = v;
    }
    g_part[bl * 512 + c] = s;
    g_part[bl * 512 + 256 + c] = q;
}

__global__ void bn_stat2(const float* __restrict__ gamma, const float* __restrict__ beta) {
    int c = threadIdx.x;
    float s = 0.f, q = 0.f;
    for (int bl = 0; bl < 400; ++bl) {
        s += g_part[bl * 512 + c];
        q += g_part[bl * 512 + 256 + c];
    }
    float mean = s * (1.f / (float)M_DIM);
    float var = q * (1.f / (float)M_DIM) - mean * mean;
    float sc = gamma[c] * rsqrtf(var + 1e-5f);
    g_scale[c] = sc;
    g_shift[c] = beta[c] - mean * sc;
}

__global__ void bn_relu_f16(int dummy) {
    int i = blockIdx.x * blockDim.x + threadIdx.x;
    if (i >= M_DIM * C1 / 4) return;
    float4 v = ((const float4*)g_sum)[i];
    int c = (i * 4) & 255;
    float r0 = fmaxf(g_scale[c + 0] * v.x + g_shift[c + 0], 0.f);
    float r1 = fmaxf(g_scale[c + 1] * v.y + g_shift[c + 1], 0.f);
    float r2 = fmaxf(g_scale[c + 2] * v.z + g_shift[c + 2], 0.f);
    float r3 = fmaxf(g_scale[c + 3] * v.w + g_shift[c + 3], 0.f);
    ((__half2*)g_ah)[PADR * C1 / 2 + i * 2 + 0] = __floats2half2_rn(r0, r1);
    ((__half2*)g_ah)[PADR * C1 / 2 + i * 2 + 1] = __floats2half2_rn(r2, r3);
}

__global__ void softmax_sum(float* __restrict__ out) {
    __shared__ float red[128][20];
    int b = blockIdx.x;
    int t = threadIdx.x;
    float acc[20];
#pragma unroll
    for (int j = 0; j < 20; ++j) acc[j] = 0.f;
    if (t < T_DIM) {
        size_t base = ((size_t)t * B_DIM + b) * 20;
        float v[20], mx = -1e30f;
#pragma unroll
        for (int j = 0; j < 20; ++j) {
            v[j] = g_logits[base + j] + g_logits[(size_t)M_DIM * 20 + base + j];
            mx = fmaxf(mx, v[j]);
        }
        float s = 0.f;
#pragma unroll
        for (int j = 0; j < 20; ++j) { v[j] = expf(v[j] - mx); s += v[j]; }
        float inv = 1.f / s;
#pragma unroll
        for (int j = 0; j < 20; ++j) acc[j] = v[j] * inv;
    }
#pragma unroll
    for (int j = 0; j < 20; ++j) red[t][j] = acc[j];
    __syncthreads();
    for (int st = 64; st > 0; st >>= 1) {
        if (t < st)
#pragma unroll
            for (int j = 0; j < 20; ++j) red[t][j] += red[t + st][j];
        __syncthreads();
    }
    if (t < 20) out[b * 20 + t] = red[0][t];
}

// ---------------- host launch ----------------
extern "C" void kernel_launch(void* const* d_in, const int* in_sizes, int n_in,
                              void* d_out, int out_size) {
    const float* x      = (const float*)d_in[0];
    const float* W1     = (const float*)d_in[1];
    const float* P1     = (const float*)d_in[2];
    const float* W2     = (const float*)d_in[3];
    const float* P2     = (const float*)d_in[4];
    const float* W3     = (const float*)d_in[5];
    const float* P3     = (const float*)d_in[6];
    const float* gamma1 = (const float*)d_in[7];
    const float* beta1  = (const float*)d_in[8];
    const float* gamma2 = (const float*)d_in[9];
    const float* beta2  = (const float*)d_in[10];
    float* out = (float*)d_out;

    __half *p_xh, *p_ah, *p_K1h, *p_K2h, *p_K3h;
    float *p_conv, *p_logits;
    cudaGetSymbolAddress((void**)&p_xh, g_xh);
    cudaGetSymbolAddress((void**)&p_ah, g_ah);
    cudaGetSymbolAddress((void**)&p_K1h, g_K1h);
    cudaGetSymbolAddress((void**)&p_K2h, g_K2h);
    cudaGetSymbolAddress((void**)&p_K3h, g_K3h);
    cudaGetSymbolAddress((void**)&p_conv, g_conv);
    cudaGetSymbolAddress((void**)&p_logits, g_logits);

    const int SM12 = 3 * (128 * 144 + 128 * 144);   // 110592 -> 2 CTAs/SM
    const int SM3  = 3 * (128 * 144 + 32 * 144);    // 69120
    cudaFuncSetAttribute((const void*)conv_mma<C0P, 128, 128, 4, 2, 256, 2, 3, 2>,
                         cudaFuncAttributeMaxDynamicSharedMemorySize, SM12);
    cudaFuncSetAttribute((const void*)conv_mma<C1, 128, 128, 4, 2, 256, 2, 3, 2>,
                         cudaFuncAttributeMaxDynamicSharedMemorySize, SM12);
    cudaFuncSetAttribute((const void*)conv_mma<C1, 128, 32, 8, 1, N3P, 1, 2, 1>,
                         cudaFuncAttributeMaxDynamicSharedMemorySize, SM3);

    conv_input<<<(ROWS_PAD * C0P / 2 + 255) / 256, 256>>>(x);
    {
        int total = 256 * C0P + 256 * C1 + N3P * C1;
        build_all<<<(total + 255) / 256, 256>>>(W1, P1, W2, P2, W3, P3);
    }

    // layer 1: 100 m-blocks x (2 n-parts x 3 k-parts) = 600 CTAs
    conv_mma<C0P, 128, 128, 4, 2, 256, 2, 3, 2><<<dim3(100, 6), 256, SM12>>>(
        p_xh, p_K1h, p_conv, 256, 256);
    bn_stat1<<<400, 256>>>(p_conv);
    bn_stat2<<<1, 256>>>(gamma1, beta1);
    bn_relu_f16<<<(M_DIM * C1 / 4 + 255) / 256, 256>>>(0);

    // layer 2
    conv_mma<C1, 128, 128, 4, 2, 256, 2, 3, 2><<<dim3(100, 6), 256, SM12>>>(
        p_ah, p_K2h, p_conv, 256, 256);
    bn_stat1<<<400, 256>>>(p_conv);
    bn_stat2<<<1, 256>>>(gamma2, beta2);
    bn_relu_f16<<<(M_DIM * C1 / 4 + 255) / 256, 256>>>(0);

    // layer 3 + head
    conv_mma<C1, 128, 32, 8, 1, N3P, 1, 2, 1><<<dim3(100, 2), 256, SM3>>>(
        p_ah, p_K3h, p_logits, 20, 20);
    softmax_sum<<<B_DIM, 128>>>(out);
}